// round 1
// baseline (speedup 1.0000x reference)
#include <cuda_runtime.h>
#include <cstddef>

// Problem constants
// input [4,1024,256] f32, A [64,64], B [64], input_state [4,256,64]
// out [4,1024,256,64] f32
// Chunked linear-recurrence transform: C=64 -> 16 chunks, 1024 bh pairs,
// GEMM: out = W[4096x128] @ Aug[128x16384]

#define NCHUNK 16
#define BHTOT  1024
#define NCOLS  (NCHUNK * BHTOT)   // 16384

// ---------------- scratch (static device memory; no runtime allocs) ------
__device__ float g_P[65 * 4096];        // P[m] = A^m, m = 1..64 (index*4096)
__device__ float g_Kvec[64 * 64];       // K_d = A^d B
__device__ float g_W[4096 * 128];       // fused [P | tri-K] matrix
__device__ float g_v[NCHUNK * BHTOT * 64];
__device__ float g_E[NCHUNK * BHTOT * 64];  // E[j] = state entering chunk j
__device__ float g_Aug[NCOLS * 128];    // per-column [e ; u] (K-major rows)

// ---------------- P[1] = A ----------------
__global__ void init_p1_kernel(const float* __restrict__ A) {
    int i = blockIdx.x * 256 + threadIdx.x;
    if (i < 4096) g_P[4096 + i] = A[i];
}

// ---------------- power doubling: P[m+i+1] = P[i+1] @ P[m], i=0..m-1 -----
__global__ void pow_stage_kernel(int m) {
    __shared__ float sA[64 * 65];
    __shared__ float sB[64 * 65];
    const int i   = blockIdx.x;
    const int tid = threadIdx.x;
    const float* Pl = g_P + (size_t)(i + 1) * 4096;
    const float* Pr = g_P + (size_t)m * 4096;
    for (int idx = tid; idx < 4096; idx += 256) {
        int n = idx >> 6, q = idx & 63;
        sA[n * 65 + q] = Pl[idx];
        sB[n * 65 + q] = Pr[idx];
    }
    __syncthreads();
    const int rg = tid >> 4;   // 16 row groups of 4
    const int cg = tid & 15;   // 16 col groups of 4
    float acc[4][4];
#pragma unroll
    for (int r = 0; r < 4; r++)
#pragma unroll
        for (int c = 0; c < 4; c++) acc[r][c] = 0.0f;
#pragma unroll 4
    for (int q = 0; q < 64; q++) {
        float a0 = sA[(rg * 4 + 0) * 65 + q];
        float a1 = sA[(rg * 4 + 1) * 65 + q];
        float a2 = sA[(rg * 4 + 2) * 65 + q];
        float a3 = sA[(rg * 4 + 3) * 65 + q];
        float b0 = sB[q * 65 + cg * 4 + 0];
        float b1 = sB[q * 65 + cg * 4 + 1];
        float b2 = sB[q * 65 + cg * 4 + 2];
        float b3 = sB[q * 65 + cg * 4 + 3];
        acc[0][0] = fmaf(a0, b0, acc[0][0]); acc[0][1] = fmaf(a0, b1, acc[0][1]);
        acc[0][2] = fmaf(a0, b2, acc[0][2]); acc[0][3] = fmaf(a0, b3, acc[0][3]);
        acc[1][0] = fmaf(a1, b0, acc[1][0]); acc[1][1] = fmaf(a1, b1, acc[1][1]);
        acc[1][2] = fmaf(a1, b2, acc[1][2]); acc[1][3] = fmaf(a1, b3, acc[1][3]);
        acc[2][0] = fmaf(a2, b0, acc[2][0]); acc[2][1] = fmaf(a2, b1, acc[2][1]);
        acc[2][2] = fmaf(a2, b2, acc[2][2]); acc[2][3] = fmaf(a2, b3, acc[2][3]);
        acc[3][0] = fmaf(a3, b0, acc[3][0]); acc[3][1] = fmaf(a3, b1, acc[3][1]);
        acc[3][2] = fmaf(a3, b2, acc[3][2]); acc[3][3] = fmaf(a3, b3, acc[3][3]);
    }
    float* Po = g_P + (size_t)(m + i + 1) * 4096;
#pragma unroll
    for (int r = 0; r < 4; r++)
#pragma unroll
        for (int c = 0; c < 4; c++)
            Po[(rg * 4 + r) * 64 + cg * 4 + c] = acc[r][c];
}

// ---------------- K_d = A^d B ----------------
__global__ void kvec_kernel(const float* __restrict__ Bv) {
    __shared__ float sB[64];
    int tid = threadIdx.x;
    if (tid < 64) sB[tid] = Bv[tid];
    __syncthreads();
    for (int idx = tid; idx < 4096; idx += 256) {
        int d = idx >> 6, n = idx & 63;
        float val;
        if (d == 0) {
            val = sB[n];
        } else {
            const float* row = g_P + (size_t)d * 4096 + n * 64;
            float a = 0.0f;
#pragma unroll 8
            for (int m2 = 0; m2 < 64; m2++) a = fmaf(row[m2], sB[m2], a);
            val = a;
        }
        g_Kvec[idx] = val;
    }
}

// ---------------- assemble W ----------------
__global__ void w_kernel() {
    int k = blockIdx.x, tid = threadIdx.x;
    for (int idx = tid; idx < 8192; idx += 256) {
        int n = idx >> 7, m = idx & 127;
        float val;
        if (m < 64) {
            val = g_P[(size_t)(k + 1) * 4096 + n * 64 + m];
        } else {
            int s = m - 64;
            val = (s <= k) ? g_Kvec[(k - s) * 64 + n] : 0.0f;
        }
        g_W[(size_t)k * 8192 + idx] = val;
    }
}

// ---------------- v_j[n] = sum_s K_{63-s}[n] * u[jC+s] ----------------
__global__ void v_kernel(const float* __restrict__ inp) {
    __shared__ float sK[4096];
    int tid = threadIdx.x;
    for (int i = tid; i < 4096; i += 256) sK[i] = g_Kvec[i];
    __syncthreads();
    int w = tid >> 5, lane = tid & 31;
    int col = blockIdx.x * 8 + w;
    int j = col >> 10, bh = col & 1023, b = bh >> 8, h = bh & 255;
    const float* up = inp + ((size_t)((b << 10) + (j << 6))) * 256 + h;
    float a0 = 0.0f, a1 = 0.0f;
#pragma unroll 4
    for (int s = 0; s < 64; s++) {
        float u = __ldg(up + (size_t)s * 256);
        a0 = fmaf(sK[(63 - s) * 64 + lane], u, a0);
        a1 = fmaf(sK[(63 - s) * 64 + lane + 32], u, a1);
    }
    g_v[(size_t)col * 64 + lane]      = a0;
    g_v[(size_t)col * 64 + lane + 32] = a1;
}

// ---------------- chunk-boundary scan (16 sequential steps, fp32) -------
__global__ void scan_kernel(const float* __restrict__ x0) {
    __shared__ float sP[64 * 65];
    __shared__ float sbuf[8][64];
    int tid = threadIdx.x;
    for (int i = tid; i < 4096; i += 256) {
        int n = i >> 6, q = i & 63;
        sP[n * 65 + q] = g_P[(size_t)64 * 4096 + i];   // P_64 = A^64
    }
    __syncthreads();
    int w = tid >> 5, lane = tid & 31;
    int bh = blockIdx.x * 8 + w;
    float s0 = x0[(size_t)bh * 64 + lane];
    float s1 = x0[(size_t)bh * 64 + lane + 32];
    g_E[(size_t)bh * 64 + lane]      = s0;
    g_E[(size_t)bh * 64 + lane + 32] = s1;
    for (int j = 1; j < 16; j++) {
        sbuf[w][lane]      = s0;
        sbuf[w][lane + 32] = s1;
        __syncwarp();
        float a0 = g_v[((size_t)(j - 1) * 1024 + bh) * 64 + lane];
        float a1 = g_v[((size_t)(j - 1) * 1024 + bh) * 64 + lane + 32];
#pragma unroll 8
        for (int q = 0; q < 64; q++) {
            float xq = sbuf[w][q];
            a0 = fmaf(sP[lane * 65 + q], xq, a0);
            a1 = fmaf(sP[(lane + 32) * 65 + q], xq, a1);
        }
        __syncwarp();
        s0 = a0; s1 = a1;
        g_E[((size_t)j * 1024 + bh) * 64 + lane]      = s0;
        g_E[((size_t)j * 1024 + bh) * 64 + lane + 32] = s1;
    }
}

// ---------------- assemble Aug[c][m] = [E[j] ; u_chunk] ----------------
__global__ void aug_kernel(const float* __restrict__ inp) {
    int idx = blockIdx.x * 256 + threadIdx.x;   // < 16384*128
    int c = idx >> 7, m = idx & 127;
    float val;
    if (m < 64) {
        val = g_E[(size_t)c * 64 + m];
    } else {
        int j = c >> 10, bh = c & 1023, b = bh >> 8, h = bh & 255;
        val = inp[(size_t)((b << 10) + (j << 6) + (m - 64)) * 256 + h];
    }
    g_Aug[idx] = val;
}

// ---------------- main GEMM: out = W @ Aug, scattered output -------------
// block: 128 threads, tile = 64 rows (one k) x 128 cols, K <= 128 with
// triangular skip (Keff = 65+k). Per-thread 8x8 register tile.
#define GEMM_SMEM_FLOATS (64 * 129 + 128 * 129)

__global__ void __launch_bounds__(128, 2) gemm_kernel(float* __restrict__ out) {
    extern __shared__ float sh[];
    float* Ws = sh;             // [64][129]  (n-major, padded)
    float* Xs = sh + 64 * 129;  // [128][129] (col-major per c', padded)
    const int tid = threadIdx.x;
    const int k   = blockIdx.y;
    const int c0  = blockIdx.x << 7;
    const int j   = c0 >> 10;
    const int b   = (c0 >> 8) & 3;
    const int h0  = c0 & 255;   // 0 or 128

    const float* Wg = g_W + (size_t)k * 8192;
    for (int idx = tid; idx < 8192; idx += 128) {
        int n = idx >> 7, m = idx & 127;
        Ws[n * 129 + m] = Wg[idx];
    }
    const float* Ag = g_Aug + (size_t)c0 * 128;
    for (int idx = tid; idx < 4096; idx += 128) {
        int c = idx >> 5, mq = (idx & 31) << 2;
        float4 v4 = *reinterpret_cast<const float4*>(Ag + (size_t)c * 128 + mq);
        float* dst = Xs + c * 129 + mq;
        dst[0] = v4.x; dst[1] = v4.y; dst[2] = v4.z; dst[3] = v4.w;
    }
    __syncthreads();

    int kmaxr = (68 + k) & ~3;
    if (kmaxr > 128) kmaxr = 128;

    const int ng = tid & 7;    // thread's rows: n = ng + 8r
    const int hg = tid >> 3;   // thread's cols: c' = hg*8 + t
    float acc[8][8];
#pragma unroll
    for (int r = 0; r < 8; r++)
#pragma unroll
        for (int t = 0; t < 8; t++) acc[r][t] = 0.0f;

    const float* Wp = Ws + ng * 129;
    const float* Xp = Xs + (hg * 8) * 129;
#pragma unroll 2
    for (int kk = 0; kk < kmaxr; kk++) {
        float wv[8], xv[8];
#pragma unroll
        for (int r = 0; r < 8; r++) wv[r] = Wp[r * (8 * 129) + kk];
#pragma unroll
        for (int t = 0; t < 8; t++) xv[t] = Xp[t * 129 + kk];
#pragma unroll
        for (int r = 0; r < 8; r++)
#pragma unroll
            for (int t = 0; t < 8; t++)
                acc[r][t] = fmaf(wv[r], xv[t], acc[r][t]);
    }

    const int trow = j * 64 + k;
    const size_t base = ((((size_t)b * 1024 + trow) * 256) + h0) * 64;
#pragma unroll
    for (int t = 0; t < 8; t++) {
        size_t hb = base + (size_t)(hg * 8 + t) * 64 + ng;
#pragma unroll
        for (int r = 0; r < 8; r++) out[hb + 8 * r] = acc[r][t];
    }
}

// ---------------- launcher ----------------
extern "C" void kernel_launch(void* const* d_in, const int* in_sizes, int n_in,
                              void* d_out, int out_size) {
    const float* inp = (const float*)d_in[0];   // [4,1024,256]
    const float* A   = (const float*)d_in[1];   // [64,64]
    const float* Bv  = (const float*)d_in[2];   // [64]
    const float* x0  = (const float*)d_in[3];   // [4,256,64]
    float* out = (float*)d_out;

    init_p1_kernel<<<16, 256>>>(A);
    pow_stage_kernel<<<1,  256>>>(1);
    pow_stage_kernel<<<2,  256>>>(2);
    pow_stage_kernel<<<4,  256>>>(4);
    pow_stage_kernel<<<8,  256>>>(8);
    pow_stage_kernel<<<16, 256>>>(16);
    pow_stage_kernel<<<32, 256>>>(32);
    kvec_kernel<<<1, 256>>>(Bv);
    w_kernel<<<64, 256>>>();
    v_kernel<<<2048, 256>>>(inp);
    scan_kernel<<<128, 256>>>(x0);
    aug_kernel<<<NCOLS * 128 / 256, 256>>>(inp);

    const size_t smem_bytes = GEMM_SMEM_FLOATS * sizeof(float);  // ~99 KB
    cudaFuncSetAttribute(gemm_kernel,
                         cudaFuncAttributeMaxDynamicSharedMemorySize,
                         (int)smem_bytes);
    dim3 grid(NCOLS / 128, 64);
    gemm_kernel<<<grid, 128, smem_bytes>>>(out);
}

// round 3
// speedup vs baseline: 1.6080x; 1.6080x over previous
#include <cuda_runtime.h>
#include <cuda_bf16.h>
#include <cstdint>
#include <cstddef>

// out = W[4096x128] @ Aug[128x16384] via mma.sync bf16 3-way split.
// W row-block k (64 rows) = [A^{k+1} | tri(K_d)]; Aug col = [E_chunk ; u_chunk].

#define NCHUNK 16
#define BHTOT  1024
#define NCOLS  (NCHUNK * BHTOT)   // 16384

// ---------------- scratch (static device memory) --------------------------
__device__ float g_P[65 * 4096];            // P[m] = A^m
__device__ float g_Kvec[64 * 64];           // K_d = A^d B
__device__ float g_v[NCHUNK * BHTOT * 64];
__device__ float g_E[NCHUNK * BHTOT * 64];
// bf16 hi/lo splits, plain row-major [row][K=128]
__device__ __align__(16) __nv_bfloat16 g_WH[64 * 8192];      // per k: 64x128
__device__ __align__(16) __nv_bfloat16 g_WL[64 * 8192];
__device__ __align__(16) __nv_bfloat16 g_AugH[(size_t)NCOLS * 128];
__device__ __align__(16) __nv_bfloat16 g_AugL[(size_t)NCOLS * 128];

// ---------------- helpers ----------------
__device__ __forceinline__ uint32_t smem_u32(const void* p) {
    uint32_t a;
    asm("{ .reg .u64 t; cvta.to.shared.u64 t, %1; cvt.u32.u64 %0, t; }"
        : "=r"(a) : "l"(p));
    return a;
}
__device__ __forceinline__ void ldsm4(uint32_t* r, uint32_t addr) {
    asm volatile("ldmatrix.sync.aligned.m8n8.x4.shared.b16 {%0,%1,%2,%3}, [%4];"
                 : "=r"(r[0]), "=r"(r[1]), "=r"(r[2]), "=r"(r[3]) : "r"(addr));
}
__device__ __forceinline__ void mma16816(float* d, const uint32_t* a,
                                         const uint32_t* b) {
    asm volatile(
        "mma.sync.aligned.m16n8k16.row.col.f32.bf16.bf16.f32 "
        "{%0,%1,%2,%3},{%4,%5,%6,%7},{%8,%9},{%0,%1,%2,%3};"
        : "+f"(d[0]), "+f"(d[1]), "+f"(d[2]), "+f"(d[3])
        : "r"(a[0]), "r"(a[1]), "r"(a[2]), "r"(a[3]), "r"(b[0]), "r"(b[1]));
}

// ---------------- P[1] = A ----------------
__global__ void init_p1_kernel(const float* __restrict__ A) {
    int i = blockIdx.x * 256 + threadIdx.x;
    if (i < 4096) g_P[4096 + i] = A[i];
}

// ---------------- power doubling: P[m+i+1] = P[i+1] @ P[m] ----------------
__global__ void pow_stage_kernel(int m) {
    __shared__ float sA[64 * 65];
    __shared__ float sB[64 * 65];
    const int i   = blockIdx.x;
    const int tid = threadIdx.x;
    const float* Pl = g_P + (size_t)(i + 1) * 4096;
    const float* Pr = g_P + (size_t)m * 4096;
    for (int idx = tid; idx < 4096; idx += 256) {
        int n = idx >> 6, q = idx & 63;
        sA[n * 65 + q] = Pl[idx];
        sB[n * 65 + q] = Pr[idx];
    }
    __syncthreads();
    const int rg = tid >> 4;
    const int cg = tid & 15;
    float acc[4][4];
#pragma unroll
    for (int r = 0; r < 4; r++)
#pragma unroll
        for (int c = 0; c < 4; c++) acc[r][c] = 0.0f;
#pragma unroll 4
    for (int q = 0; q < 64; q++) {
        float a0 = sA[(rg * 4 + 0) * 65 + q];
        float a1 = sA[(rg * 4 + 1) * 65 + q];
        float a2 = sA[(rg * 4 + 2) * 65 + q];
        float a3 = sA[(rg * 4 + 3) * 65 + q];
        float b0 = sB[q * 65 + cg * 4 + 0];
        float b1 = sB[q * 65 + cg * 4 + 1];
        float b2 = sB[q * 65 + cg * 4 + 2];
        float b3 = sB[q * 65 + cg * 4 + 3];
        acc[0][0] = fmaf(a0, b0, acc[0][0]); acc[0][1] = fmaf(a0, b1, acc[0][1]);
        acc[0][2] = fmaf(a0, b2, acc[0][2]); acc[0][3] = fmaf(a0, b3, acc[0][3]);
        acc[1][0] = fmaf(a1, b0, acc[1][0]); acc[1][1] = fmaf(a1, b1, acc[1][1]);
        acc[1][2] = fmaf(a1, b2, acc[1][2]); acc[1][3] = fmaf(a1, b3, acc[1][3]);
        acc[2][0] = fmaf(a2, b0, acc[2][0]); acc[2][1] = fmaf(a2, b1, acc[2][1]);
        acc[2][2] = fmaf(a2, b2, acc[2][2]); acc[2][3] = fmaf(a2, b3, acc[2][3]);
        acc[3][0] = fmaf(a3, b0, acc[3][0]); acc[3][1] = fmaf(a3, b1, acc[3][1]);
        acc[3][2] = fmaf(a3, b2, acc[3][2]); acc[3][3] = fmaf(a3, b3, acc[3][3]);
    }
    float* Po = g_P + (size_t)(m + i + 1) * 4096;
#pragma unroll
    for (int r = 0; r < 4; r++)
#pragma unroll
        for (int c = 0; c < 4; c++)
            Po[(rg * 4 + r) * 64 + cg * 4 + c] = acc[r][c];
}

// ---------------- K_d = A^d B ----------------
__global__ void kvec_kernel(const float* __restrict__ Bv) {
    __shared__ float sB[64];
    int tid = threadIdx.x;
    if (tid < 64) sB[tid] = Bv[tid];
    __syncthreads();
    for (int idx = tid; idx < 4096; idx += 256) {
        int d = idx >> 6, n = idx & 63;
        float val;
        if (d == 0) {
            val = sB[n];
        } else {
            const float* row = g_P + (size_t)d * 4096 + n * 64;
            float a = 0.0f;
#pragma unroll 8
            for (int m2 = 0; m2 < 64; m2++) a = fmaf(row[m2], sB[m2], a);
            val = a;
        }
        g_Kvec[idx] = val;
    }
}

// ---------------- assemble W (bf16 hi/lo, row-major [n][128]) -------------
__global__ void w_kernel() {
    int k = blockIdx.x, tid = threadIdx.x;
    for (int idx = tid; idx < 8192; idx += 256) {
        int n = idx >> 7, m = idx & 127;
        float val;
        if (m < 64) {
            val = g_P[(size_t)(k + 1) * 4096 + n * 64 + m];
        } else {
            int s = m - 64;
            val = (s <= k) ? g_Kvec[(k - s) * 64 + n] : 0.0f;
        }
        __nv_bfloat16 hi = __float2bfloat16(val);
        __nv_bfloat16 lo = __float2bfloat16(val - __bfloat162float(hi));
        g_WH[(size_t)k * 8192 + idx] = hi;
        g_WL[(size_t)k * 8192 + idx] = lo;
    }
}

// ---------------- v_j[n] = sum_s K_{63-s}[n] * u[jC+s] ----------------
__global__ void v_kernel(const float* __restrict__ inp) {
    __shared__ float sK[4096];
    int tid = threadIdx.x;
    for (int i = tid; i < 4096; i += 256) sK[i] = g_Kvec[i];
    __syncthreads();
    int w = tid >> 5, lane = tid & 31;
    int col = blockIdx.x * 8 + w;
    int j = col >> 10, bh = col & 1023, b = bh >> 8, h = bh & 255;
    const float* up = inp + ((size_t)((b << 10) + (j << 6))) * 256 + h;
    float a0 = 0.0f, a1 = 0.0f;
#pragma unroll 4
    for (int s = 0; s < 64; s++) {
        float u = __ldg(up + (size_t)s * 256);
        a0 = fmaf(sK[(63 - s) * 64 + lane], u, a0);
        a1 = fmaf(sK[(63 - s) * 64 + lane + 32], u, a1);
    }
    g_v[(size_t)col * 64 + lane]      = a0;
    g_v[(size_t)col * 64 + lane + 32] = a1;
}

// ---------------- chunk-boundary scan (16 steps, fp32) --------------------
__global__ void scan_kernel(const float* __restrict__ x0) {
    __shared__ float sP[64 * 65];
    __shared__ float sbuf[8][64];
    int tid = threadIdx.x;
    for (int i = tid; i < 4096; i += 256) {
        int n = i >> 6, q = i & 63;
        sP[n * 65 + q] = g_P[(size_t)64 * 4096 + i];
    }
    __syncthreads();
    int w = tid >> 5, lane = tid & 31;
    int bh = blockIdx.x * 8 + w;
    float s0 = x0[(size_t)bh * 64 + lane];
    float s1 = x0[(size_t)bh * 64 + lane + 32];
    g_E[(size_t)bh * 64 + lane]      = s0;
    g_E[(size_t)bh * 64 + lane + 32] = s1;
    for (int j = 1; j < 16; j++) {
        sbuf[w][lane]      = s0;
        sbuf[w][lane + 32] = s1;
        __syncwarp();
        float a0 = g_v[((size_t)(j - 1) * 1024 + bh) * 64 + lane];
        float a1 = g_v[((size_t)(j - 1) * 1024 + bh) * 64 + lane + 32];
#pragma unroll 8
        for (int q = 0; q < 64; q++) {
            float xq = sbuf[w][q];
            a0 = fmaf(sP[lane * 65 + q], xq, a0);
            a1 = fmaf(sP[(lane + 32) * 65 + q], xq, a1);
        }
        __syncwarp();
        s0 = a0; s1 = a1;
        g_E[((size_t)j * 1024 + bh) * 64 + lane]      = s0;
        g_E[((size_t)j * 1024 + bh) * 64 + lane + 32] = s1;
    }
}

// ---------------- assemble Aug (bf16 hi/lo, row-major [c][128]) -----------
__global__ void aug_kernel(const float* __restrict__ inp) {
    int idx = blockIdx.x * 256 + threadIdx.x;   // < 16384*128
    int c = idx >> 7, m = idx & 127;
    float val;
    if (m < 64) {
        val = g_E[(size_t)c * 64 + m];
    } else {
        int j = c >> 10, bh = c & 1023, b = bh >> 8, h = bh & 255;
        val = inp[(size_t)((b << 10) + (j << 6) + (m - 64)) * 256 + h];
    }
    __nv_bfloat16 hi = __float2bfloat16(val);
    __nv_bfloat16 lo = __float2bfloat16(val - __bfloat162float(hi));
    g_AugH[idx] = hi;
    g_AugL[idx] = lo;
}

// ---------------- mma.sync GEMM ----------------
// CTA: 128 Aug cols (M) x 4 k-blocks (N=256). 8 warps: wm = wid&1 (M half),
// wn = wid>>1 (k-block). Warp tile 64x64. smem rows pitch 272 B
// (conflict-free ldmatrix). Triangular K skip per k-block.
#define PITCH    272
#define SM_AUGH  0
#define SM_AUGL  34816
#define SM_W     69632          // per block: hi 17408 + lo 17408
#define GEMM_SMEM 208896

__global__ void __launch_bounds__(256, 1) gemm_kernel(float* __restrict__ out) {
    extern __shared__ char smraw[];
    const uint32_t base = smem_u32(smraw);
    const int tid  = threadIdx.x;
    const int wid  = tid >> 5;
    const int lane = tid & 31;
    const int T  = blockIdx.x;        // column tile (128 Aug cols)
    const int kg = blockIdx.y;        // group of 4 k-blocks

    // ---- stage operands in smem (row-major, pitch 272 B) ----
    {
        const uint4* sAH = reinterpret_cast<const uint4*>(g_AugH) + (size_t)T * 2048;
        const uint4* sAL = reinterpret_cast<const uint4*>(g_AugL) + (size_t)T * 2048;
        for (int i = tid; i < 2048; i += 256) {
            int row = i >> 4, q = i & 15;
            *reinterpret_cast<uint4*>(smraw + SM_AUGH + row * PITCH + q * 16) = __ldg(sAH + i);
            *reinterpret_cast<uint4*>(smraw + SM_AUGL + row * PITCH + q * 16) = __ldg(sAL + i);
        }
#pragma unroll
        for (int kl = 0; kl < 4; kl++) {
            int k = kg * 4 + kl;
            const uint4* sWH = reinterpret_cast<const uint4*>(g_WH) + (size_t)k * 1024;
            const uint4* sWL = reinterpret_cast<const uint4*>(g_WL) + (size_t)k * 1024;
            char* dW = smraw + SM_W + kl * 34816;
            for (int i = tid; i < 1024; i += 256) {
                int row = i >> 4, q = i & 15;
                *reinterpret_cast<uint4*>(dW + row * PITCH + q * 16)         = __ldg(sWH + i);
                *reinterpret_cast<uint4*>(dW + 17408 + row * PITCH + q * 16) = __ldg(sWL + i);
            }
        }
    }
    __syncthreads();

    const int wm = wid & 1;           // M half (64 cols)
    const int wn = wid >> 1;          // k-block within group
    const int k  = kg * 4 + wn;
    const int steps = (80 + k) >> 4;  // ceil((65+k)/16): 5..8

    // lane-fixed ldmatrix base addresses
    const uint32_t aRow = (lane & 7) + ((lane >> 3) & 1) * 8;
    const uint32_t aOff = ((lane >> 4) & 1) * 16;
    const uint32_t aH = base + SM_AUGH + (wm * 64 + aRow) * PITCH + aOff;
    const uint32_t aL = aH + (SM_AUGL - SM_AUGH);
    const uint32_t bRow = (lane & 7) + ((lane >> 4) & 1) * 8;
    const uint32_t bOff = ((lane >> 3) & 1) * 16;
    const uint32_t wH = base + SM_W + wn * 34816 + bRow * PITCH + bOff;
    const uint32_t wL = wH + 17408;

    float acc[4][8][4];
#pragma unroll
    for (int mt = 0; mt < 4; mt++)
#pragma unroll
        for (int nt = 0; nt < 8; nt++)
#pragma unroll
            for (int r = 0; r < 4; r++) acc[mt][nt][r] = 0.0f;

#pragma unroll 1
    for (int s = 0; s < steps; s++) {
        uint32_t ah[4][4], al[4][4];
#pragma unroll
        for (int mt = 0; mt < 4; mt++) {
            ldsm4(ah[mt], aH + mt * (16 * PITCH) + s * 32);
            ldsm4(al[mt], aL + mt * (16 * PITCH) + s * 32);
        }
#pragma unroll
        for (int np = 0; np < 4; np++) {
            uint32_t wh[4], wl[4];
            ldsm4(wh, wH + np * (16 * PITCH) + s * 32);
            ldsm4(wl, wL + np * (16 * PITCH) + s * 32);
#pragma unroll
            for (int mt = 0; mt < 4; mt++) {
                mma16816(acc[mt][2 * np],     ah[mt], wh);
                mma16816(acc[mt][2 * np + 1], ah[mt], wh + 2);
                mma16816(acc[mt][2 * np],     ah[mt], wl);
                mma16816(acc[mt][2 * np + 1], ah[mt], wl + 2);
                mma16816(acc[mt][2 * np],     al[mt], wh);
                mma16816(acc[mt][2 * np + 1], al[mt], wh + 2);
            }
        }
    }

    // ---- epilogue: D frags -> coalesced float2 stores ----
    // c = T*128 + cl; j=T>>3, b=(T>>1)&3, h = (T&1)*128 + cl; t = j*64+k
    const int j  = T >> 3;
    const int b  = (T >> 1) & 3;
    const int h0 = (T & 1) << 7;
    const int t  = j * 64 + k;
    const size_t rowBase = ((size_t)(b * 1024 + t)) * 16384;  // *256*64
    const int rbase = lane >> 2;
    const int ncol  = (lane & 3) * 2;
#pragma unroll
    for (int mt = 0; mt < 4; mt++) {
        const int cl0 = wm * 64 + mt * 16 + rbase;
        float* p0 = out + rowBase + (size_t)(h0 + cl0) * 64 + ncol;
        float* p1 = p0 + 8 * 64;
#pragma unroll
        for (int nt = 0; nt < 8; nt++) {
            float2 v0 = make_float2(acc[mt][nt][0], acc[mt][nt][1]);
            float2 v1 = make_float2(acc[mt][nt][2], acc[mt][nt][3]);
            *reinterpret_cast<float2*>(p0 + nt * 8) = v0;
            *reinterpret_cast<float2*>(p1 + nt * 8) = v1;
        }
    }
}

// ---------------- launcher ----------------
extern "C" void kernel_launch(void* const* d_in, const int* in_sizes, int n_in,
                              void* d_out, int out_size) {
    const float* inp = (const float*)d_in[0];   // [4,1024,256]
    const float* A   = (const float*)d_in[1];   // [64,64]
    const float* Bv  = (const float*)d_in[2];   // [64]
    const float* x0  = (const float*)d_in[3];   // [4,256,64]
    float* out = (float*)d_out;

    init_p1_kernel<<<16, 256>>>(A);
    pow_stage_kernel<<<1,  256>>>(1);
    pow_stage_kernel<<<2,  256>>>(2);
    pow_stage_kernel<<<4,  256>>>(4);
    pow_stage_kernel<<<8,  256>>>(8);
    pow_stage_kernel<<<16, 256>>>(16);
    pow_stage_kernel<<<32, 256>>>(32);
    kvec_kernel<<<1, 256>>>(Bv);
    w_kernel<<<64, 256>>>();
    v_kernel<<<2048, 256>>>(inp);
    scan_kernel<<<128, 256>>>(x0);
    aug_kernel<<<NCOLS * 128 / 256, 256>>>(inp);

    cudaFuncSetAttribute(gemm_kernel,
                         cudaFuncAttributeMaxDynamicSharedMemorySize, GEMM_SMEM);
    dim3 grid(128, 16);
    gemm_kernel<<<grid, 256, GEMM_SMEM>>>(out);
}

// round 4
// speedup vs baseline: 1.7592x; 1.0940x over previous
#include <cuda_runtime.h>
#include <cuda_bf16.h>
#include <cstdint>
#include <cstddef>

// out = W[4096x128] @ Aug[128x16384] via mma.sync bf16 3-way split.
// W row-block k (64 rows) = [A^{k+1} | tri(K_d)]; Aug col = [E_chunk ; u_chunk].

#define NCHUNK 16
#define BHTOT  1024
#define NCOLS  (NCHUNK * BHTOT)   // 16384

// ---------------- scratch (static device memory) --------------------------
__device__ float g_P[65 * 4096];            // P[m] = A^m
__device__ float g_Kvec[64 * 64];           // K_d = A^d B
__device__ float g_v[NCHUNK * BHTOT * 64];
__device__ float g_E[NCHUNK * BHTOT * 64];
// bf16 hi/lo splits, plain row-major [row][K=128]
__device__ __align__(16) __nv_bfloat16 g_WH[64 * 8192];      // per k: 64x128
__device__ __align__(16) __nv_bfloat16 g_WL[64 * 8192];
__device__ __align__(16) __nv_bfloat16 g_AugH[(size_t)NCOLS * 128];
__device__ __align__(16) __nv_bfloat16 g_AugL[(size_t)NCOLS * 128];

// ---------------- helpers ----------------
__device__ __forceinline__ uint32_t smem_u32(const void* p) {
    uint32_t a;
    asm("{ .reg .u64 t; cvta.to.shared.u64 t, %1; cvt.u32.u64 %0, t; }"
        : "=r"(a) : "l"(p));
    return a;
}
__device__ __forceinline__ void ldsm4(uint32_t* r, uint32_t addr) {
    asm volatile("ldmatrix.sync.aligned.m8n8.x4.shared.b16 {%0,%1,%2,%3}, [%4];"
                 : "=r"(r[0]), "=r"(r[1]), "=r"(r[2]), "=r"(r[3]) : "r"(addr));
}
__device__ __forceinline__ void mma16816(float* d, const uint32_t* a,
                                         const uint32_t* b) {
    asm volatile(
        "mma.sync.aligned.m16n8k16.row.col.f32.bf16.bf16.f32 "
        "{%0,%1,%2,%3},{%4,%5,%6,%7},{%8,%9},{%0,%1,%2,%3};"
        : "+f"(d[0]), "+f"(d[1]), "+f"(d[2]), "+f"(d[3])
        : "r"(a[0]), "r"(a[1]), "r"(a[2]), "r"(a[3]), "r"(b[0]), "r"(b[1]));
}
__device__ __forceinline__ void cp16(uint32_t dst, const void* src) {
    asm volatile("cp.async.cg.shared.global [%0], [%1], 16;"
                 :: "r"(dst), "l"(src));
}
__device__ __forceinline__ void cp_wait_all() {
    asm volatile("cp.async.commit_group;\ncp.async.wait_group 0;" ::: "memory");
}

// ---------------- squarings: g_P[1]=A, g_P[2],4,8,16,32 -------------------
__global__ void __launch_bounds__(1024, 1) squarings_kernel(const float* __restrict__ A) {
    __shared__ float s0[64 * 65];
    __shared__ float s1[64 * 65];
    const int tid = threadIdx.x;
    for (int i = tid; i < 4096; i += 1024) {
        float v = A[i];
        s0[(i >> 6) * 65 + (i & 63)] = v;
        g_P[4096 + i] = v;
    }
    __syncthreads();
    float* src = s0;
    float* dst = s1;
    int p = 2;
    const int r  = tid >> 4;
    const int c0 = (tid & 15) * 4;
#pragma unroll 1
    for (int st = 0; st < 5; st++) {
        float a0 = 0, a1 = 0, a2 = 0, a3 = 0;
#pragma unroll 8
        for (int q = 0; q < 64; q++) {
            float av = src[r * 65 + q];
            a0 = fmaf(av, src[q * 65 + c0 + 0], a0);
            a1 = fmaf(av, src[q * 65 + c0 + 1], a1);
            a2 = fmaf(av, src[q * 65 + c0 + 2], a2);
            a3 = fmaf(av, src[q * 65 + c0 + 3], a3);
        }
        dst[r * 65 + c0 + 0] = a0;
        dst[r * 65 + c0 + 1] = a1;
        dst[r * 65 + c0 + 2] = a2;
        dst[r * 65 + c0 + 3] = a3;
        float* Po = g_P + (size_t)p * 4096 + r * 64 + c0;
        Po[0] = a0; Po[1] = a1; Po[2] = a2; Po[3] = a3;
        __syncthreads();
        float* t = src; src = dst; dst = t;
        p <<= 1;
    }
}

// ---------------- powers: CTA c computes P[c+1] (binary product), K_{c+1} -
__global__ void __launch_bounds__(256, 1) powers_kernel(const float* __restrict__ Bv) {
    __shared__ float cur[64 * 65];
    __shared__ float fac[64 * 65];
    __shared__ float bs[64];
    const int c = blockIdx.x;     // 0..63
    const int e = c + 1;          // 1..64
    const int tid = threadIdx.x;

    int low, rem;
    if (e == 64) { low = 32; rem = 32; }
    else         { low = e & (-e); rem = e - low; }

    for (int i = tid; i < 4096; i += 256)
        cur[(i >> 6) * 65 + (i & 63)] = g_P[(size_t)low * 4096 + i];
    if (tid < 64) bs[tid] = Bv[tid];

    const int rg = tid >> 4;
    const int cg = tid & 15;
    while (rem) {
        int b = rem & (-rem);
        rem -= b;
        for (int i = tid; i < 4096; i += 256)
            fac[(i >> 6) * 65 + (i & 63)] = g_P[(size_t)b * 4096 + i];
        __syncthreads();
        float acc[4][4];
#pragma unroll
        for (int r = 0; r < 4; r++)
#pragma unroll
            for (int cc = 0; cc < 4; cc++) acc[r][cc] = 0.0f;
#pragma unroll 4
        for (int q = 0; q < 64; q++) {
            float a0 = cur[(rg * 4 + 0) * 65 + q];
            float a1 = cur[(rg * 4 + 1) * 65 + q];
            float a2 = cur[(rg * 4 + 2) * 65 + q];
            float a3 = cur[(rg * 4 + 3) * 65 + q];
            float b0 = fac[q * 65 + cg * 4 + 0];
            float b1 = fac[q * 65 + cg * 4 + 1];
            float b2 = fac[q * 65 + cg * 4 + 2];
            float b3 = fac[q * 65 + cg * 4 + 3];
            acc[0][0] = fmaf(a0, b0, acc[0][0]); acc[0][1] = fmaf(a0, b1, acc[0][1]);
            acc[0][2] = fmaf(a0, b2, acc[0][2]); acc[0][3] = fmaf(a0, b3, acc[0][3]);
            acc[1][0] = fmaf(a1, b0, acc[1][0]); acc[1][1] = fmaf(a1, b1, acc[1][1]);
            acc[1][2] = fmaf(a1, b2, acc[1][2]); acc[1][3] = fmaf(a1, b3, acc[1][3]);
            acc[2][0] = fmaf(a2, b0, acc[2][0]); acc[2][1] = fmaf(a2, b1, acc[2][1]);
            acc[2][2] = fmaf(a2, b2, acc[2][2]); acc[2][3] = fmaf(a2, b3, acc[2][3]);
            acc[3][0] = fmaf(a3, b0, acc[3][0]); acc[3][1] = fmaf(a3, b1, acc[3][1]);
            acc[3][2] = fmaf(a3, b2, acc[3][2]); acc[3][3] = fmaf(a3, b3, acc[3][3]);
        }
        __syncthreads();
#pragma unroll
        for (int r = 0; r < 4; r++)
#pragma unroll
            for (int cc = 0; cc < 4; cc++)
                cur[(rg * 4 + r) * 65 + cg * 4 + cc] = acc[r][cc];
        __syncthreads();
    }
    // store P[e]
    for (int i = tid; i < 4096; i += 256)
        g_P[(size_t)e * 4096 + i] = cur[(i >> 6) * 65 + (i & 63)];
    // K vectors: K_{e} = P[e] @ B (e<=63); CTA 0 also writes K_0 = B
    __syncthreads();
    if (e <= 63) {
        for (int n = tid; n < 64; n += 256) {
            float a = 0.0f;
#pragma unroll 8
            for (int q = 0; q < 64; q++) a = fmaf(cur[n * 65 + q], bs[q], a);
            g_Kvec[e * 64 + n] = a;
        }
    }
    if (c == 0 && tid < 64) g_Kvec[tid] = bs[tid];
}

// ---------------- assemble W (bf16 hi/lo, row-major [n][128]) -------------
__global__ void w_kernel() {
    int k = blockIdx.x, tid = threadIdx.x;
    for (int idx = tid; idx < 8192; idx += 256) {
        int n = idx >> 7, m = idx & 127;
        float val;
        if (m < 64) {
            val = g_P[(size_t)(k + 1) * 4096 + n * 64 + m];
        } else {
            int s = m - 64;
            val = (s <= k) ? g_Kvec[(k - s) * 64 + n] : 0.0f;
        }
        __nv_bfloat16 hi = __float2bfloat16(val);
        __nv_bfloat16 lo = __float2bfloat16(val - __bfloat162float(hi));
        g_WH[(size_t)k * 8192 + idx] = hi;
        g_WL[(size_t)k * 8192 + idx] = lo;
    }
}

// ---------------- v_j[n] = sum_s K_{63-s}[n] * u[jC+s] ----------------
__global__ void v_kernel(const float* __restrict__ inp) {
    __shared__ float sK[4096];
    int tid = threadIdx.x;
    for (int i = tid; i < 4096; i += 256) sK[i] = g_Kvec[i];
    __syncthreads();
    int w = tid >> 5, lane = tid & 31;
    int col = blockIdx.x * 8 + w;
    int j = col >> 10, bh = col & 1023, b = bh >> 8, h = bh & 255;
    const float* up = inp + ((size_t)((b << 10) + (j << 6))) * 256 + h;
    float a0 = 0.0f, a1 = 0.0f;
#pragma unroll 4
    for (int s = 0; s < 64; s++) {
        float u = __ldg(up + (size_t)s * 256);
        a0 = fmaf(sK[(63 - s) * 64 + lane], u, a0);
        a1 = fmaf(sK[(63 - s) * 64 + lane + 32], u, a1);
    }
    g_v[(size_t)col * 64 + lane]      = a0;
    g_v[(size_t)col * 64 + lane + 32] = a1;
}

// ---------------- chunk-boundary scan (16 steps, fp32) --------------------
__global__ void scan_kernel(const float* __restrict__ x0) {
    __shared__ float sP[64 * 65];
    __shared__ float sbuf[8][64];
    int tid = threadIdx.x;
    for (int i = tid; i < 4096; i += 256) {
        int n = i >> 6, q = i & 63;
        sP[n * 65 + q] = g_P[(size_t)64 * 4096 + i];
    }
    __syncthreads();
    int w = tid >> 5, lane = tid & 31;
    int bh = blockIdx.x * 8 + w;
    float s0 = x0[(size_t)bh * 64 + lane];
    float s1 = x0[(size_t)bh * 64 + lane + 32];
    g_E[(size_t)bh * 64 + lane]      = s0;
    g_E[(size_t)bh * 64 + lane + 32] = s1;
    for (int j = 1; j < 16; j++) {
        sbuf[w][lane]      = s0;
        sbuf[w][lane + 32] = s1;
        __syncwarp();
        float a0 = g_v[((size_t)(j - 1) * 1024 + bh) * 64 + lane];
        float a1 = g_v[((size_t)(j - 1) * 1024 + bh) * 64 + lane + 32];
#pragma unroll 8
        for (int q = 0; q < 64; q++) {
            float xq = sbuf[w][q];
            a0 = fmaf(sP[lane * 65 + q], xq, a0);
            a1 = fmaf(sP[(lane + 32) * 65 + q], xq, a1);
        }
        __syncwarp();
        s0 = a0; s1 = a1;
        g_E[((size_t)j * 1024 + bh) * 64 + lane]      = s0;
        g_E[((size_t)j * 1024 + bh) * 64 + lane + 32] = s1;
    }
}

// ---------------- assemble Aug (bf16 hi/lo, row-major [c][128]) -----------
__global__ void aug_kernel(const float* __restrict__ inp) {
    int idx = blockIdx.x * 256 + threadIdx.x;   // < 16384*128
    int c = idx >> 7, m = idx & 127;
    float val;
    if (m < 64) {
        val = g_E[(size_t)c * 64 + m];
    } else {
        int j = c >> 10, bh = c & 1023, b = bh >> 8, h = bh & 255;
        val = inp[(size_t)((b << 10) + (j << 6) + (m - 64)) * 256 + h];
    }
    __nv_bfloat16 hi = __float2bfloat16(val);
    __nv_bfloat16 lo = __float2bfloat16(val - __bfloat162float(hi));
    g_AugH[idx] = hi;
    g_AugL[idx] = lo;
}

// ---------------- mma.sync GEMM ----------------
// CTA: 128 Aug cols (M) x 4 k-blocks (N=256). 8 warps: wm = wid&1 (M half),
// wn = wid>>1 (k-block). Warp tile 64x64. smem rows pitch 272 B.
// steps = 5 + (kg>>2) is uniform per CTA -> compile-time template dispatch.
#define PITCH    272
#define SM_AUGH  0
#define SM_AUGL  34816
#define SM_W     69632          // per block: hi 17408 + lo 17408
#define GEMM_SMEM 208896

template <int STEPS>
__device__ __forceinline__ void gemm_body(
    uint32_t aH, uint32_t aL, uint32_t wHa, uint32_t wLa,
    float* __restrict__ out, int T, int k, int wm, int lane)
{
    float acc[4][8][4];
#pragma unroll
    for (int mt = 0; mt < 4; mt++)
#pragma unroll
        for (int nt = 0; nt < 8; nt++)
#pragma unroll
            for (int r = 0; r < 4; r++) acc[mt][nt][r] = 0.0f;

#pragma unroll
    for (int s = 0; s < STEPS; s++) {
        uint32_t ah[4][4], al[4][4];
#pragma unroll
        for (int mt = 0; mt < 4; mt++) {
            ldsm4(ah[mt], aH + mt * (16 * PITCH) + s * 32);
            ldsm4(al[mt], aL + mt * (16 * PITCH) + s * 32);
        }
#pragma unroll
        for (int np = 0; np < 4; np++) {
            uint32_t wh[4], wl[4];
            ldsm4(wh, wHa + np * (16 * PITCH) + s * 32);
            ldsm4(wl, wLa + np * (16 * PITCH) + s * 32);
            // split-major ordering: same-acc reuse distance = 8 MMAs
#pragma unroll
            for (int mt = 0; mt < 4; mt++) {
                mma16816(acc[mt][2 * np],     ah[mt], wh);
                mma16816(acc[mt][2 * np + 1], ah[mt], wh + 2);
            }
#pragma unroll
            for (int mt = 0; mt < 4; mt++) {
                mma16816(acc[mt][2 * np],     ah[mt], wl);
                mma16816(acc[mt][2 * np + 1], ah[mt], wl + 2);
            }
#pragma unroll
            for (int mt = 0; mt < 4; mt++) {
                mma16816(acc[mt][2 * np],     al[mt], wh);
                mma16816(acc[mt][2 * np + 1], al[mt], wh + 2);
            }
        }
    }

    // epilogue: D frags -> coalesced float2 stores
    const int j  = T >> 3;
    const int b  = (T >> 1) & 3;
    const int h0 = (T & 1) << 7;
    const int t  = j * 64 + k;
    const size_t rowBase = ((size_t)(b * 1024 + t)) * 16384;  // *256*64
    const int rbase = lane >> 2;
    const int ncol  = (lane & 3) * 2;
#pragma unroll
    for (int mt = 0; mt < 4; mt++) {
        const int cl0 = wm * 64 + mt * 16 + rbase;
        float* p0 = out + rowBase + (size_t)(h0 + cl0) * 64 + ncol;
        float* p1 = p0 + 8 * 64;
#pragma unroll
        for (int nt = 0; nt < 8; nt++) {
            *reinterpret_cast<float2*>(p0 + nt * 8) =
                make_float2(acc[mt][nt][0], acc[mt][nt][1]);
            *reinterpret_cast<float2*>(p1 + nt * 8) =
                make_float2(acc[mt][nt][2], acc[mt][nt][3]);
        }
    }
}

__global__ void __launch_bounds__(256, 1) gemm_kernel(float* __restrict__ out) {
    extern __shared__ char smraw[];
    const uint32_t base = smem_u32(smraw);
    const int tid  = threadIdx.x;
    const int wid  = tid >> 5;
    const int lane = tid & 31;
    const int T  = blockIdx.x;        // column tile (128 Aug cols)
    const int kg = blockIdx.y;        // group of 4 k-blocks

    // ---- stage operands in smem via cp.async (row-major, pitch 272 B) ----
    {
        const uint4* sAH = reinterpret_cast<const uint4*>(g_AugH) + (size_t)T * 2048;
        const uint4* sAL = reinterpret_cast<const uint4*>(g_AugL) + (size_t)T * 2048;
        for (int i = tid; i < 2048; i += 256) {
            int row = i >> 4, q = i & 15;
            cp16(base + SM_AUGH + row * PITCH + q * 16, sAH + i);
            cp16(base + SM_AUGL + row * PITCH + q * 16, sAL + i);
        }
#pragma unroll
        for (int kl = 0; kl < 4; kl++) {
            int k = kg * 4 + kl;
            const uint4* sWH = reinterpret_cast<const uint4*>(g_WH) + (size_t)k * 1024;
            const uint4* sWL = reinterpret_cast<const uint4*>(g_WL) + (size_t)k * 1024;
            uint32_t dW = base + SM_W + kl * 34816;
            for (int i = tid; i < 1024; i += 256) {
                int row = i >> 4, q = i & 15;
                cp16(dW + row * PITCH + q * 16, sWH + i);
                cp16(dW + 17408 + row * PITCH + q * 16, sWL + i);
            }
        }
    }
    cp_wait_all();
    __syncthreads();

    const int wm = wid & 1;           // M half (64 cols)
    const int wn = wid >> 1;          // k-block within group
    const int k  = kg * 4 + wn;

    // lane-fixed ldmatrix base addresses
    const uint32_t aRow = (lane & 7) + ((lane >> 3) & 1) * 8;
    const uint32_t aOff = ((lane >> 4) & 1) * 16;
    const uint32_t aH = base + SM_AUGH + (wm * 64 + aRow) * PITCH + aOff;
    const uint32_t aL = aH + (SM_AUGL - SM_AUGH);
    const uint32_t bRow = (lane & 7) + ((lane >> 4) & 1) * 8;
    const uint32_t bOff = ((lane >> 3) & 1) * 16;
    const uint32_t wHa = base + SM_W + wn * 34816 + bRow * PITCH + bOff;
    const uint32_t wLa = wHa + 17408;

    const int sv = kg >> 2;           // steps variant: 5 + sv
    if      (sv == 0) gemm_body<5>(aH, aL, wHa, wLa, out, T, k, wm, lane);
    else if (sv == 1) gemm_body<6>(aH, aL, wHa, wLa, out, T, k, wm, lane);
    else if (sv == 2) gemm_body<7>(aH, aL, wHa, wLa, out, T, k, wm, lane);
    else              gemm_body<8>(aH, aL, wHa, wLa, out, T, k, wm, lane);
}

// ---------------- launcher ----------------
extern "C" void kernel_launch(void* const* d_in, const int* in_sizes, int n_in,
                              void* d_out, int out_size) {
    const float* inp = (const float*)d_in[0];   // [4,1024,256]
    const float* A   = (const float*)d_in[1];   // [64,64]
    const float* Bv  = (const float*)d_in[2];   // [64]
    const float* x0  = (const float*)d_in[3];   // [4,256,64]
    float* out = (float*)d_out;

    squarings_kernel<<<1, 1024>>>(A);
    powers_kernel<<<64, 256>>>(Bv);
    w_kernel<<<64, 256>>>();
    v_kernel<<<2048, 256>>>(inp);
    scan_kernel<<<128, 256>>>(x0);
    aug_kernel<<<NCOLS * 128 / 256, 256>>>(inp);

    cudaFuncSetAttribute(gemm_kernel,
                         cudaFuncAttributeMaxDynamicSharedMemorySize, GEMM_SMEM);
    dim3 grid(128, 16);
    gemm_kernel<<<grid, 256, GEMM_SMEM>>>(out);
}

// round 5
// speedup vs baseline: 2.6639x; 1.5143x over previous
#include <cuda_runtime.h>
#include <cuda_bf16.h>
#include <cstdint>
#include <cstddef>

// out = W[4096x128] @ Aug[128x16384] via mma.sync bf16 3-way split.
// W row-block k (64 rows) = [A^{k+1} | tri(K_d)]; Aug col = [E_chunk ; u_chunk].

#define NCHUNK 16
#define BHTOT  1024
#define NCOLS  (NCHUNK * BHTOT)   // 16384

// ---------------- scratch (static device memory) --------------------------
__device__ float g_P[65 * 4096];            // P[m] = A^m
__device__ float g_Kvec[64 * 64];           // K_d = A^d B
__device__ float g_v[NCHUNK * BHTOT * 64];
__device__ float g_E[NCHUNK * BHTOT * 64];
__device__ float g_UT[(size_t)BHTOT * 1024];     // input transposed [bh][seq]
// bf16 hi/lo splits, plain row-major [row][K=128]
__device__ __align__(16) __nv_bfloat16 g_WH[64 * 8192];      // per k: 64x128
__device__ __align__(16) __nv_bfloat16 g_WL[64 * 8192];
__device__ __align__(16) __nv_bfloat16 g_AugH[(size_t)NCOLS * 128];
__device__ __align__(16) __nv_bfloat16 g_AugL[(size_t)NCOLS * 128];

// ---------------- helpers ----------------
__device__ __forceinline__ uint32_t smem_u32(const void* p) {
    uint32_t a;
    asm("{ .reg .u64 t; cvta.to.shared.u64 t, %1; cvt.u32.u64 %0, t; }"
        : "=r"(a) : "l"(p));
    return a;
}
__device__ __forceinline__ void ldsm4(uint32_t* r, uint32_t addr) {
    asm volatile("ldmatrix.sync.aligned.m8n8.x4.shared.b16 {%0,%1,%2,%3}, [%4];"
                 : "=r"(r[0]), "=r"(r[1]), "=r"(r[2]), "=r"(r[3]) : "r"(addr));
}
__device__ __forceinline__ void mma16816(float* d, const uint32_t* a,
                                         const uint32_t* b) {
    asm volatile(
        "mma.sync.aligned.m16n8k16.row.col.f32.bf16.bf16.f32 "
        "{%0,%1,%2,%3},{%4,%5,%6,%7},{%8,%9},{%0,%1,%2,%3};"
        : "+f"(d[0]), "+f"(d[1]), "+f"(d[2]), "+f"(d[3])
        : "r"(a[0]), "r"(a[1]), "r"(a[2]), "r"(a[3]), "r"(b[0]), "r"(b[1]));
}
__device__ __forceinline__ void cp16(uint32_t dst, const void* src) {
    asm volatile("cp.async.cg.shared.global [%0], [%1], 16;"
                 :: "r"(dst), "l"(src));
}
__device__ __forceinline__ void cp_commit() {
    asm volatile("cp.async.commit_group;" ::: "memory");
}
template <int N>
__device__ __forceinline__ void cp_wait_n() {
    asm volatile("cp.async.wait_group %0;" :: "n"(N) : "memory");
}

// ---------------- squarings: g_P[1]=A, g_P[2],4,8,16,32 -------------------
__global__ void __launch_bounds__(1024, 1) squarings_kernel(const float* __restrict__ A) {
    __shared__ float s0[64 * 65];
    __shared__ float s1[64 * 65];
    const int tid = threadIdx.x;
    for (int i = tid; i < 4096; i += 1024) {
        float v = A[i];
        s0[(i >> 6) * 65 + (i & 63)] = v;
        g_P[4096 + i] = v;
    }
    __syncthreads();
    float* src = s0;
    float* dst = s1;
    int p = 2;
    const int r  = tid >> 4;
    const int c0 = (tid & 15) * 4;
#pragma unroll 1
    for (int st = 0; st < 5; st++) {
        float a0 = 0, a1 = 0, a2 = 0, a3 = 0;
#pragma unroll 8
        for (int q = 0; q < 64; q++) {
            float av = src[r * 65 + q];
            a0 = fmaf(av, src[q * 65 + c0 + 0], a0);
            a1 = fmaf(av, src[q * 65 + c0 + 1], a1);
            a2 = fmaf(av, src[q * 65 + c0 + 2], a2);
            a3 = fmaf(av, src[q * 65 + c0 + 3], a3);
        }
        dst[r * 65 + c0 + 0] = a0;
        dst[r * 65 + c0 + 1] = a1;
        dst[r * 65 + c0 + 2] = a2;
        dst[r * 65 + c0 + 3] = a3;
        float* Po = g_P + (size_t)p * 4096 + r * 64 + c0;
        Po[0] = a0; Po[1] = a1; Po[2] = a2; Po[3] = a3;
        __syncthreads();
        float* t = src; src = dst; dst = t;
        p <<= 1;
    }
}

// ---------------- powers: CTA c computes P[c+1] (binary product), K_{c+1} -
__global__ void __launch_bounds__(256, 1) powers_kernel(const float* __restrict__ Bv) {
    __shared__ float cur[64 * 65];
    __shared__ float fac[64 * 65];
    __shared__ float bs[64];
    const int c = blockIdx.x;     // 0..63
    const int e = c + 1;          // 1..64
    const int tid = threadIdx.x;

    int low, rem;
    if (e == 64) { low = 32; rem = 32; }
    else         { low = e & (-e); rem = e - low; }

    for (int i = tid; i < 4096; i += 256)
        cur[(i >> 6) * 65 + (i & 63)] = g_P[(size_t)low * 4096 + i];
    if (tid < 64) bs[tid] = Bv[tid];

    const int rg = tid >> 4;
    const int cg = tid & 15;
    while (rem) {
        int b = rem & (-rem);
        rem -= b;
        for (int i = tid; i < 4096; i += 256)
            fac[(i >> 6) * 65 + (i & 63)] = g_P[(size_t)b * 4096 + i];
        __syncthreads();
        float acc[4][4];
#pragma unroll
        for (int r = 0; r < 4; r++)
#pragma unroll
            for (int cc = 0; cc < 4; cc++) acc[r][cc] = 0.0f;
#pragma unroll 4
        for (int q = 0; q < 64; q++) {
            float a0 = cur[(rg * 4 + 0) * 65 + q];
            float a1 = cur[(rg * 4 + 1) * 65 + q];
            float a2 = cur[(rg * 4 + 2) * 65 + q];
            float a3 = cur[(rg * 4 + 3) * 65 + q];
            float b0 = fac[q * 65 + cg * 4 + 0];
            float b1 = fac[q * 65 + cg * 4 + 1];
            float b2 = fac[q * 65 + cg * 4 + 2];
            float b3 = fac[q * 65 + cg * 4 + 3];
            acc[0][0] = fmaf(a0, b0, acc[0][0]); acc[0][1] = fmaf(a0, b1, acc[0][1]);
            acc[0][2] = fmaf(a0, b2, acc[0][2]); acc[0][3] = fmaf(a0, b3, acc[0][3]);
            acc[1][0] = fmaf(a1, b0, acc[1][0]); acc[1][1] = fmaf(a1, b1, acc[1][1]);
            acc[1][2] = fmaf(a1, b2, acc[1][2]); acc[1][3] = fmaf(a1, b3, acc[1][3]);
            acc[2][0] = fmaf(a2, b0, acc[2][0]); acc[2][1] = fmaf(a2, b1, acc[2][1]);
            acc[2][2] = fmaf(a2, b2, acc[2][2]); acc[2][3] = fmaf(a2, b3, acc[2][3]);
            acc[3][0] = fmaf(a3, b0, acc[3][0]); acc[3][1] = fmaf(a3, b1, acc[3][1]);
            acc[3][2] = fmaf(a3, b2, acc[3][2]); acc[3][3] = fmaf(a3, b3, acc[3][3]);
        }
        __syncthreads();
#pragma unroll
        for (int r = 0; r < 4; r++)
#pragma unroll
            for (int cc = 0; cc < 4; cc++)
                cur[(rg * 4 + r) * 65 + cg * 4 + cc] = acc[r][cc];
        __syncthreads();
    }
    for (int i = tid; i < 4096; i += 256)
        g_P[(size_t)e * 4096 + i] = cur[(i >> 6) * 65 + (i & 63)];
    __syncthreads();
    if (e <= 63) {
        for (int n = tid; n < 64; n += 256) {
            float a = 0.0f;
#pragma unroll 8
            for (int q = 0; q < 64; q++) a = fmaf(cur[n * 65 + q], bs[q], a);
            g_Kvec[e * 64 + n] = a;
        }
    }
    if (c == 0 && tid < 64) g_Kvec[tid] = bs[tid];
}

// ---------------- assemble W (bf16 hi/lo, row-major [n][128]) -------------
__global__ void w_kernel() {
    int k = blockIdx.x, tid = threadIdx.x;
    for (int idx = tid; idx < 8192; idx += 256) {
        int n = idx >> 7, m = idx & 127;
        float val;
        if (m < 64) {
            val = g_P[(size_t)(k + 1) * 4096 + n * 64 + m];
        } else {
            int s = m - 64;
            val = (s <= k) ? g_Kvec[(k - s) * 64 + n] : 0.0f;
        }
        __nv_bfloat16 hi = __float2bfloat16(val);
        __nv_bfloat16 lo = __float2bfloat16(val - __bfloat162float(hi));
        g_WH[(size_t)k * 8192 + idx] = hi;
        g_WL[(size_t)k * 8192 + idx] = lo;
    }
}

// ---------------- transpose input -> g_UT[bh][seq] ------------------------
__global__ void transpose_kernel(const float* __restrict__ inp) {
    __shared__ float tile[32][33];
    const int tx = threadIdx.x, ty = threadIdx.y;     // 32 x 8
    const int t0 = blockIdx.x * 32, h0 = blockIdx.y * 32, b = blockIdx.z;
    const float* src = inp + (size_t)b * 1024 * 256;
#pragma unroll
    for (int i2 = 0; i2 < 4; i2++) {
        int row = ty + 8 * i2;
        tile[row][tx] = src[(size_t)(t0 + row) * 256 + h0 + tx];
    }
    __syncthreads();
#pragma unroll
    for (int i2 = 0; i2 < 4; i2++) {
        int hr = ty + 8 * i2;
        g_UT[(size_t)(b * 256 + h0 + hr) * 1024 + t0 + tx] = tile[tx][hr];
    }
}

// ---------------- v_j[n] = sum_s K_{63-s}[n] * u[jC+s]  (coalesced) -------
__global__ void v_kernel() {
    __shared__ float sK[4096];
    __shared__ float su[8][64];
    int tid = threadIdx.x;
    for (int i = tid; i < 4096; i += 256) sK[i] = g_Kvec[i];
    __syncthreads();
    int w = tid >> 5, lane = tid & 31;
    int col = blockIdx.x * 8 + w;
    int j = col >> 10, bh = col & 1023;
    const float* up = g_UT + (size_t)bh * 1024 + (j << 6);
    su[w][lane]      = up[lane];
    su[w][lane + 32] = up[lane + 32];
    __syncwarp();
    float a0 = 0.0f, a1 = 0.0f;
#pragma unroll 8
    for (int s = 0; s < 64; s++) {
        float u = su[w][s];
        a0 = fmaf(sK[(63 - s) * 64 + lane], u, a0);
        a1 = fmaf(sK[(63 - s) * 64 + lane + 32], u, a1);
    }
    g_v[(size_t)col * 64 + lane]      = a0;
    g_v[(size_t)col * 64 + lane + 32] = a1;
}

// ---------------- chunk-boundary scan (16 steps, fp32) --------------------
__global__ void scan_kernel(const float* __restrict__ x0) {
    __shared__ float sP[64 * 65];
    __shared__ float sbuf[8][64];
    int tid = threadIdx.x;
    for (int i = tid; i < 4096; i += 256) {
        int n = i >> 6, q = i & 63;
        sP[n * 65 + q] = g_P[(size_t)64 * 4096 + i];
    }
    __syncthreads();
    int w = tid >> 5, lane = tid & 31;
    int bh = blockIdx.x * 8 + w;
    float s0 = x0[(size_t)bh * 64 + lane];
    float s1 = x0[(size_t)bh * 64 + lane + 32];
    g_E[(size_t)bh * 64 + lane]      = s0;
    g_E[(size_t)bh * 64 + lane + 32] = s1;
    for (int j = 1; j < 16; j++) {
        sbuf[w][lane]      = s0;
        sbuf[w][lane + 32] = s1;
        __syncwarp();
        float a0 = g_v[((size_t)(j - 1) * 1024 + bh) * 64 + lane];
        float a1 = g_v[((size_t)(j - 1) * 1024 + bh) * 64 + lane + 32];
#pragma unroll 8
        for (int q = 0; q < 64; q++) {
            float xq = sbuf[w][q];
            a0 = fmaf(sP[lane * 65 + q], xq, a0);
            a1 = fmaf(sP[(lane + 32) * 65 + q], xq, a1);
        }
        __syncwarp();
        s0 = a0; s1 = a1;
        g_E[((size_t)j * 1024 + bh) * 64 + lane]      = s0;
        g_E[((size_t)j * 1024 + bh) * 64 + lane + 32] = s1;
    }
}

// ---------------- assemble Aug (bf16 hi/lo, coalesced reads) --------------
__global__ void aug_kernel() {
    int idx = blockIdx.x * 256 + threadIdx.x;   // < 16384*128
    int c = idx >> 7, m = idx & 127;
    float val;
    if (m < 64) {
        val = g_E[(size_t)c * 64 + m];
    } else {
        int j = c >> 10, bh = c & 1023;
        val = g_UT[(size_t)bh * 1024 + (j << 6) + (m - 64)];
    }
    __nv_bfloat16 hi = __float2bfloat16(val);
    __nv_bfloat16 lo = __float2bfloat16(val - __bfloat162float(hi));
    g_AugH[idx] = hi;
    g_AugL[idx] = lo;
}

// ---------------- mma.sync GEMM ----------------
// CTA (512 thr, 16 warps): 128 Aug cols x 4 k-blocks (256 W rows).
// Warp: wm=wid>>3 (M half 64), ns=(wid>>2)&1 (32-row N half), kb=wid&3.
// smem rows pitch 272 B: Aug hi rows 0-127, lo 128-255; W at row 256+:
// per kb: hi 64 rows, lo 64 rows. cp.async staged by K-step pairs.
#define PITCH    272
#define SM_WROW  256
#define GEMM_SMEM (768 * 272)    // 208896

__device__ __forceinline__ void load_pair(uint32_t base, int tid, int T,
                                          int kg, int p) {
    for (int i = tid; i < 3072; i += 512) {
        int row = i >> 2, q = i & 3;
        uint32_t dst = base + row * PITCH + p * 64 + q * 16;
        const __nv_bfloat16* src;
        if (row < 128) {
            src = g_AugH + ((size_t)(T * 128 + row)) * 128;
        } else if (row < 256) {
            src = g_AugL + ((size_t)(T * 128 + row - 128)) * 128;
        } else {
            int w = row - 256;                 // 0..511
            int kb = w >> 7, hl = (w >> 6) & 1, r = w & 63;
            const __nv_bfloat16* g = hl ? g_WL : g_WH;
            src = g + ((size_t)((kg * 4 + kb) * 64 + r)) * 128;
        }
        cp16(dst, src + p * 32 + q * 8);
    }
    cp_commit();
}

template <int NP>
__device__ __forceinline__ void wait_pair(int p) {
    int pending = NP - 1 - p;
    if (pending <= 0)      cp_wait_n<0>();
    else if (pending == 1) cp_wait_n<1>();
    else if (pending == 2) cp_wait_n<2>();
    else                   cp_wait_n<3>();
}

template <int STEPS>
__device__ __forceinline__ void gemm_body(uint32_t base, int tid, int T,
                                          int kg, float* __restrict__ out) {
    const int wid = tid >> 5, lane = tid & 31;
    const int kb = wid & 3, ns = (wid >> 2) & 1, wm = wid >> 3;
    constexpr int NP = (STEPS + 1) / 2;

#pragma unroll
    for (int p = 0; p < NP; p++) load_pair(base, tid, T, kg, p);

    const uint32_t aRow = (lane & 7) + ((lane >> 3) & 1) * 8;
    const uint32_t aOff = ((lane >> 4) & 1) * 16;
    const uint32_t aH = base + (wm * 64 + aRow) * PITCH + aOff;
    const uint32_t aL = aH + 128 * PITCH;
    const uint32_t bRow = (lane & 7) + ((lane >> 4) & 1) * 8;
    const uint32_t bOff = ((lane >> 3) & 1) * 16;
    const uint32_t wHa = base + (SM_WROW + kb * 128 + ns * 32 + bRow) * PITCH + bOff;
    const uint32_t wLa = wHa + 64 * PITCH;

    float acc[4][4][4];
#pragma unroll
    for (int mt = 0; mt < 4; mt++)
#pragma unroll
        for (int nt = 0; nt < 4; nt++)
#pragma unroll
            for (int r = 0; r < 4; r++) acc[mt][nt][r] = 0.0f;

#pragma unroll
    for (int s = 0; s < STEPS; s++) {
        if ((s & 1) == 0) {
            wait_pair<NP>(s >> 1);
            __syncthreads();
        }
        uint32_t ah[4][4], al[4][4];
#pragma unroll
        for (int mt = 0; mt < 4; mt++) {
            ldsm4(ah[mt], aH + mt * (16 * PITCH) + s * 32);
            ldsm4(al[mt], aL + mt * (16 * PITCH) + s * 32);
        }
        uint32_t wh[2][4], wl[2][4];
        ldsm4(wh[0], wHa + s * 32);
        ldsm4(wh[1], wHa + 16 * PITCH + s * 32);
        ldsm4(wl[0], wLa + s * 32);
        ldsm4(wl[1], wLa + 16 * PITCH + s * 32);
        // split-major: same-acc reuse distance = 16 MMAs
#pragma unroll
        for (int mt = 0; mt < 4; mt++)
#pragma unroll
            for (int nt = 0; nt < 4; nt++)
                mma16816(acc[mt][nt], ah[mt], &wh[nt >> 1][(nt & 1) * 2]);
#pragma unroll
        for (int mt = 0; mt < 4; mt++)
#pragma unroll
            for (int nt = 0; nt < 4; nt++)
                mma16816(acc[mt][nt], ah[mt], &wl[nt >> 1][(nt & 1) * 2]);
#pragma unroll
        for (int mt = 0; mt < 4; mt++)
#pragma unroll
            for (int nt = 0; nt < 4; nt++)
                mma16816(acc[mt][nt], al[mt], &wh[nt >> 1][(nt & 1) * 2]);
    }

    // ---- epilogue: coalesced float2 stores ----
    const int j  = T >> 3;
    const int b  = (T >> 1) & 3;
    const int h0 = (T & 1) << 7;
    const int k  = kg * 4 + kb;
    const int t  = j * 64 + k;
    const size_t rowBase = (size_t)(b * 1024 + t) * 16384;
    const int rbase = lane >> 2;
    const int ncol  = ns * 32 + (lane & 3) * 2;
#pragma unroll
    for (int mt = 0; mt < 4; mt++) {
        const int cl0 = wm * 64 + mt * 16 + rbase;
        float* p0 = out + rowBase + (size_t)(h0 + cl0) * 64 + ncol;
        float* p1 = p0 + 8 * 64;
#pragma unroll
        for (int nt = 0; nt < 4; nt++) {
            *reinterpret_cast<float2*>(p0 + nt * 8) =
                make_float2(acc[mt][nt][0], acc[mt][nt][1]);
            *reinterpret_cast<float2*>(p1 + nt * 8) =
                make_float2(acc[mt][nt][2], acc[mt][nt][3]);
        }
    }
}

__global__ void __launch_bounds__(512, 1) gemm_kernel(float* __restrict__ out) {
    extern __shared__ char smraw[];
    const uint32_t base = smem_u32(smraw);
    const int tid = threadIdx.x;
    const int T   = blockIdx.x;       // column tile
    const int kg  = blockIdx.y;       // group of 4 k-blocks

    const int sv = kg >> 2;           // steps = 5 + sv (uniform per CTA)
    if      (sv == 0) gemm_body<5>(base, tid, T, kg, out);
    else if (sv == 1) gemm_body<6>(base, tid, T, kg, out);
    else if (sv == 2) gemm_body<7>(base, tid, T, kg, out);
    else              gemm_body<8>(base, tid, T, kg, out);
}

// ---------------- launcher ----------------
extern "C" void kernel_launch(void* const* d_in, const int* in_sizes, int n_in,
                              void* d_out, int out_size) {
    const float* inp = (const float*)d_in[0];   // [4,1024,256]
    const float* A   = (const float*)d_in[1];   // [64,64]
    const float* Bv  = (const float*)d_in[2];   // [64]
    const float* x0  = (const float*)d_in[3];   // [4,256,64]
    float* out = (float*)d_out;

    squarings_kernel<<<1, 1024>>>(A);
    transpose_kernel<<<dim3(32, 8, 4), dim3(32, 8)>>>(inp);
    powers_kernel<<<64, 256>>>(Bv);
    w_kernel<<<64, 256>>>();
    v_kernel<<<2048, 256>>>();
    scan_kernel<<<128, 256>>>(x0);
    aug_kernel<<<NCOLS * 128 / 256, 256>>>();

    cudaFuncSetAttribute(gemm_kernel,
                         cudaFuncAttributeMaxDynamicSharedMemorySize, GEMM_SMEM);
    dim3 grid(128, 16);
    gemm_kernel<<<grid, 512, GEMM_SMEM>>>(out);
}

// round 6
// speedup vs baseline: 3.2293x; 1.2122x over previous
#include <cuda_runtime.h>
#include <cuda_fp16.h>
#include <cstdint>
#include <cstddef>

// out = W[4096x128] @ Aug[128x16384] via mma.sync fp16 2-term split:
// D = fp16(Aug) x (Wh + Wl).  W row-block k = [A^{k+1} | tri(K_d)];
// Aug col = [E_chunk ; u_chunk].

#define NCHUNK 16
#define BHTOT  1024
#define NCOLS  (NCHUNK * BHTOT)   // 16384

// ---------------- scratch (static device memory) --------------------------
__device__ float g_P[65 * 4096];            // P[m] = A^m
__device__ float g_Kvec[64 * 64];           // K_d = A^d B
__device__ float g_UT[(size_t)BHTOT * 1024];     // input transposed [bh][seq]
__device__ __align__(16) __half g_WH[64 * 8192];      // W fp16 hi, per k 64x128
__device__ __align__(16) __half g_WL[64 * 8192];      // W fp16 lo
__device__ __align__(16) __half g_AugH[(size_t)NCOLS * 128];  // fp16(Aug)

// ---------------- helpers ----------------
__device__ __forceinline__ uint32_t smem_u32(const void* p) {
    uint32_t a;
    asm("{ .reg .u64 t; cvta.to.shared.u64 t, %1; cvt.u32.u64 %0, t; }"
        : "=r"(a) : "l"(p));
    return a;
}
__device__ __forceinline__ void ldsm4(uint32_t* r, uint32_t addr) {
    asm volatile("ldmatrix.sync.aligned.m8n8.x4.shared.b16 {%0,%1,%2,%3}, [%4];"
                 : "=r"(r[0]), "=r"(r[1]), "=r"(r[2]), "=r"(r[3]) : "r"(addr));
}
__device__ __forceinline__ void mma16816(float* d, const uint32_t* a,
                                         const uint32_t* b) {
    asm volatile(
        "mma.sync.aligned.m16n8k16.row.col.f32.f16.f16.f32 "
        "{%0,%1,%2,%3},{%4,%5,%6,%7},{%8,%9},{%0,%1,%2,%3};"
        : "+f"(d[0]), "+f"(d[1]), "+f"(d[2]), "+f"(d[3])
        : "r"(a[0]), "r"(a[1]), "r"(a[2]), "r"(a[3]), "r"(b[0]), "r"(b[1]));
}
__device__ __forceinline__ void cp16(uint32_t dst, const void* src) {
    asm volatile("cp.async.cg.shared.global [%0], [%1], 16;"
                 :: "r"(dst), "l"(src));
}
__device__ __forceinline__ void cp_commit() {
    asm volatile("cp.async.commit_group;" ::: "memory");
}
template <int N>
__device__ __forceinline__ void cp_wait_n() {
    asm volatile("cp.async.wait_group %0;" :: "n"(N) : "memory");
}

// ---------------- squarings: g_P[1]=A, g_P[2],4,8,16,32 -------------------
__global__ void __launch_bounds__(1024, 1) squarings_kernel(const float* __restrict__ A) {
    __shared__ float s0[64 * 65];
    __shared__ float s1[64 * 65];
    const int tid = threadIdx.x;
    for (int i = tid; i < 4096; i += 1024) {
        float v = A[i];
        s0[(i >> 6) * 65 + (i & 63)] = v;
        g_P[4096 + i] = v;
    }
    __syncthreads();
    float* src = s0;
    float* dst = s1;
    int p = 2;
    const int r  = tid >> 4;
    const int c0 = (tid & 15) * 4;
#pragma unroll 1
    for (int st = 0; st < 5; st++) {
        float a0 = 0, a1 = 0, a2 = 0, a3 = 0;
#pragma unroll 8
        for (int q = 0; q < 64; q++) {
            float av = src[r * 65 + q];
            a0 = fmaf(av, src[q * 65 + c0 + 0], a0);
            a1 = fmaf(av, src[q * 65 + c0 + 1], a1);
            a2 = fmaf(av, src[q * 65 + c0 + 2], a2);
            a3 = fmaf(av, src[q * 65 + c0 + 3], a3);
        }
        dst[r * 65 + c0 + 0] = a0;
        dst[r * 65 + c0 + 1] = a1;
        dst[r * 65 + c0 + 2] = a2;
        dst[r * 65 + c0 + 3] = a3;
        float* Po = g_P + (size_t)p * 4096 + r * 64 + c0;
        Po[0] = a0; Po[1] = a1; Po[2] = a2; Po[3] = a3;
        __syncthreads();
        float* t = src; src = dst; dst = t;
        p <<= 1;
    }
}

// ---------------- transpose input -> g_UT[bh][seq] + Aug u-half -----------
__global__ void transpose_kernel(const float* __restrict__ inp) {
    __shared__ float tile[32][33];
    const int tx = threadIdx.x, ty = threadIdx.y;     // 32 x 8
    const int t0 = blockIdx.x * 32, h0 = blockIdx.y * 32, b = blockIdx.z;
    const float* src = inp + (size_t)b * 1024 * 256;
#pragma unroll
    for (int i2 = 0; i2 < 4; i2++) {
        int row = ty + 8 * i2;
        tile[row][tx] = src[(size_t)(t0 + row) * 256 + h0 + tx];
    }
    __syncthreads();
    const int j = t0 >> 6;            // chunk (t0 is 32-aligned, within one chunk)
    const int s0 = t0 & 63;
#pragma unroll
    for (int i2 = 0; i2 < 4; i2++) {
        int hr = ty + 8 * i2;
        int bh = b * 256 + h0 + hr;
        float v = tile[tx][hr];
        g_UT[(size_t)bh * 1024 + t0 + tx] = v;
        g_AugH[(size_t)(j * 1024 + bh) * 128 + 64 + s0 + tx] = __float2half(v);
    }
}

// ---------------- powers: CTA c computes P[c+1] (binary product), K_{c+1} -
__global__ void __launch_bounds__(256, 1) powers_kernel(const float* __restrict__ Bv) {
    __shared__ float cur[64 * 65];
    __shared__ float fac[64 * 65];
    __shared__ float bs[64];
    const int c = blockIdx.x;     // 0..63
    const int e = c + 1;          // 1..64
    const int tid = threadIdx.x;

    int low, rem;
    if (e == 64) { low = 32; rem = 32; }
    else         { low = e & (-e); rem = e - low; }

    for (int i = tid; i < 4096; i += 256)
        cur[(i >> 6) * 65 + (i & 63)] = g_P[(size_t)low * 4096 + i];
    if (tid < 64) bs[tid] = Bv[tid];

    const int rg = tid >> 4;
    const int cg = tid & 15;
    while (rem) {
        int b = rem & (-rem);
        rem -= b;
        for (int i = tid; i < 4096; i += 256)
            fac[(i >> 6) * 65 + (i & 63)] = g_P[(size_t)b * 4096 + i];
        __syncthreads();
        float acc[4][4];
#pragma unroll
        for (int r = 0; r < 4; r++)
#pragma unroll
            for (int cc = 0; cc < 4; cc++) acc[r][cc] = 0.0f;
#pragma unroll 4
        for (int q = 0; q < 64; q++) {
            float a0 = cur[(rg * 4 + 0) * 65 + q];
            float a1 = cur[(rg * 4 + 1) * 65 + q];
            float a2 = cur[(rg * 4 + 2) * 65 + q];
            float a3 = cur[(rg * 4 + 3) * 65 + q];
            float b0 = fac[q * 65 + cg * 4 + 0];
            float b1 = fac[q * 65 + cg * 4 + 1];
            float b2 = fac[q * 65 + cg * 4 + 2];
            float b3 = fac[q * 65 + cg * 4 + 3];
            acc[0][0] = fmaf(a0, b0, acc[0][0]); acc[0][1] = fmaf(a0, b1, acc[0][1]);
            acc[0][2] = fmaf(a0, b2, acc[0][2]); acc[0][3] = fmaf(a0, b3, acc[0][3]);
            acc[1][0] = fmaf(a1, b0, acc[1][0]); acc[1][1] = fmaf(a1, b1, acc[1][1]);
            acc[1][2] = fmaf(a1, b2, acc[1][2]); acc[1][3] = fmaf(a1, b3, acc[1][3]);
            acc[2][0] = fmaf(a2, b0, acc[2][0]); acc[2][1] = fmaf(a2, b1, acc[2][1]);
            acc[2][2] = fmaf(a2, b2, acc[2][2]); acc[2][3] = fmaf(a2, b3, acc[2][3]);
            acc[3][0] = fmaf(a3, b0, acc[3][0]); acc[3][1] = fmaf(a3, b1, acc[3][1]);
            acc[3][2] = fmaf(a3, b2, acc[3][2]); acc[3][3] = fmaf(a3, b3, acc[3][3]);
        }
        __syncthreads();
#pragma unroll
        for (int r = 0; r < 4; r++)
#pragma unroll
            for (int cc = 0; cc < 4; cc++)
                cur[(rg * 4 + r) * 65 + cg * 4 + cc] = acc[r][cc];
        __syncthreads();
    }
    for (int i = tid; i < 4096; i += 256)
        g_P[(size_t)e * 4096 + i] = cur[(i >> 6) * 65 + (i & 63)];
    __syncthreads();
    if (e <= 63) {
        for (int n = tid; n < 64; n += 256) {
            float a = 0.0f;
#pragma unroll 8
            for (int q = 0; q < 64; q++) a = fmaf(cur[n * 65 + q], bs[q], a);
            g_Kvec[e * 64 + n] = a;
        }
    }
    if (c == 0 && tid < 64) g_Kvec[tid] = bs[tid];
}

// ---------------- assemble W (fp16 hi/lo, row-major [n][128]) -------------
// grid 512: 8 CTAs per k, each handles 1024 of 8192 elements
__global__ void w_kernel() {
    int k = blockIdx.x >> 3, seg = blockIdx.x & 7, tid = threadIdx.x;
    int i0 = seg * 1024;
    for (int idx = i0 + tid; idx < i0 + 1024; idx += 256) {
        int n = idx >> 7, m = idx & 127;
        float val;
        if (m < 64) {
            val = g_P[(size_t)(k + 1) * 4096 + n * 64 + m];
        } else {
            int s = m - 64;
            val = (s <= k) ? g_Kvec[(k - s) * 64 + n] : 0.0f;
        }
        __half hi = __float2half(val);
        __half lo = __float2half(val - __half2float(hi));
        g_WH[(size_t)k * 8192 + idx] = hi;
        g_WL[(size_t)k * 8192 + idx] = lo;
    }
}

// ---------------- fused v + boundary scan + Aug E-half --------------------
__global__ void vscan_kernel(const float* __restrict__ x0) {
    __shared__ float sK[4096];
    __shared__ float sP[64 * 65];
    __shared__ float su[8][64];
    __shared__ float sbuf[8][64];
    int tid = threadIdx.x;
    for (int i = tid; i < 4096; i += 256) {
        sK[i] = g_Kvec[i];
        sP[(i >> 6) * 65 + (i & 63)] = g_P[(size_t)64 * 4096 + i];
    }
    __syncthreads();
    int w = tid >> 5, lane = tid & 31;
    int bh = blockIdx.x * 8 + w;
    const float* up = g_UT + (size_t)bh * 1024;
    float s0 = x0[(size_t)bh * 64 + lane];
    float s1 = x0[(size_t)bh * 64 + lane + 32];
    g_AugH[(size_t)bh * 128 + lane]      = __float2half(s0);
    g_AugH[(size_t)bh * 128 + lane + 32] = __float2half(s1);
#pragma unroll 1
    for (int j = 1; j < 16; j++) {
        // v_{j-1}
        su[w][lane]      = up[(j - 1) * 64 + lane];
        su[w][lane + 32] = up[(j - 1) * 64 + lane + 32];
        sbuf[w][lane]      = s0;
        sbuf[w][lane + 32] = s1;
        __syncwarp();
        float a0 = 0.0f, a1 = 0.0f;
#pragma unroll 8
        for (int s = 0; s < 64; s++) {
            float u = su[w][s];
            a0 = fmaf(sK[(63 - s) * 64 + lane], u, a0);
            a1 = fmaf(sK[(63 - s) * 64 + lane + 32], u, a1);
        }
        // E[j] = P64 * E[j-1] + v_{j-1}
#pragma unroll 8
        for (int q = 0; q < 64; q++) {
            float xq = sbuf[w][q];
            a0 = fmaf(sP[lane * 65 + q], xq, a0);
            a1 = fmaf(sP[(lane + 32) * 65 + q], xq, a1);
        }
        __syncwarp();
        s0 = a0; s1 = a1;
        g_AugH[(size_t)(j * 1024 + bh) * 128 + lane]      = __float2half(s0);
        g_AugH[(size_t)(j * 1024 + bh) * 128 + lane + 32] = __float2half(s1);
    }
}

// ---------------- mma.sync GEMM (fp16 2-term) ----------------
// CTA (512 thr, 16 warps): 128 Aug cols x 4 k-blocks (256 W rows).
// Warp: wm=wid>>3 (M half 64), ns=(wid>>2)&1 (32-row N half), kb=wid&3.
// smem pitch 272 B: Aug rows 0-127; W rows 128+: per kb hi 64 + lo 64.
#define PITCH    272
#define SM_WROW  128
#define GEMM_SMEM (640 * 272)    // 174080

__device__ __forceinline__ void load_pair(uint32_t base, int tid, int T,
                                          int kg, int p) {
    for (int i = tid; i < 2560; i += 512) {
        int row = i >> 2, q = i & 3;
        uint32_t dst = base + row * PITCH + p * 64 + q * 16;
        const __half* src;
        if (row < 128) {
            src = g_AugH + ((size_t)(T * 128 + row)) * 128;
        } else {
            int w2 = row - 128;                // 0..511
            int kb = w2 >> 7, hl = (w2 >> 6) & 1, r = w2 & 63;
            const __half* g = hl ? g_WL : g_WH;
            src = g + ((size_t)((kg * 4 + kb) * 64 + r)) * 128;
        }
        cp16(dst, src + p * 32 + q * 8);
    }
    cp_commit();
}

template <int NP>
__device__ __forceinline__ void wait_pair(int p) {
    int pending = NP - 1 - p;
    if (pending <= 0)      cp_wait_n<0>();
    else if (pending == 1) cp_wait_n<1>();
    else if (pending == 2) cp_wait_n<2>();
    else                   cp_wait_n<3>();
}

template <int STEPS>
__device__ __forceinline__ void gemm_body(uint32_t base, int tid, int T,
                                          int kg, float* __restrict__ out) {
    const int wid = tid >> 5, lane = tid & 31;
    const int kb = wid & 3, ns = (wid >> 2) & 1, wm = wid >> 3;
    constexpr int NP = (STEPS + 1) / 2;

#pragma unroll
    for (int p = 0; p < NP; p++) load_pair(base, tid, T, kg, p);

    const uint32_t aRow = (lane & 7) + ((lane >> 3) & 1) * 8;
    const uint32_t aOff = ((lane >> 4) & 1) * 16;
    const uint32_t aH = base + (wm * 64 + aRow) * PITCH + aOff;
    const uint32_t bRow = (lane & 7) + ((lane >> 4) & 1) * 8;
    const uint32_t bOff = ((lane >> 3) & 1) * 16;
    const uint32_t wHa = base + (SM_WROW + kb * 128 + ns * 32 + bRow) * PITCH + bOff;
    const uint32_t wLa = wHa + 64 * PITCH;

    float acc[4][4][4];
#pragma unroll
    for (int mt = 0; mt < 4; mt++)
#pragma unroll
        for (int nt = 0; nt < 4; nt++)
#pragma unroll
            for (int r = 0; r < 4; r++) acc[mt][nt][r] = 0.0f;

#pragma unroll
    for (int s = 0; s < STEPS; s++) {
        if ((s & 1) == 0) {
            wait_pair<NP>(s >> 1);
            __syncthreads();
        }
        uint32_t ah[4][4];
#pragma unroll
        for (int mt = 0; mt < 4; mt++)
            ldsm4(ah[mt], aH + mt * (16 * PITCH) + s * 32);
        uint32_t wh[2][4], wl[2][4];
        ldsm4(wh[0], wHa + s * 32);
        ldsm4(wh[1], wHa + 16 * PITCH + s * 32);
        ldsm4(wl[0], wLa + s * 32);
        ldsm4(wl[1], wLa + 16 * PITCH + s * 32);
        // hi pass then lo pass: same-acc reuse distance = 16 MMAs
#pragma unroll
        for (int mt = 0; mt < 4; mt++)
#pragma unroll
            for (int nt = 0; nt < 4; nt++)
                mma16816(acc[mt][nt], ah[mt], &wh[nt >> 1][(nt & 1) * 2]);
#pragma unroll
        for (int mt = 0; mt < 4; mt++)
#pragma unroll
            for (int nt = 0; nt < 4; nt++)
                mma16816(acc[mt][nt], ah[mt], &wl[nt >> 1][(nt & 1) * 2]);
    }

    // ---- epilogue: coalesced float2 stores ----
    const int j  = T >> 3;
    const int b  = (T >> 1) & 3;
    const int h0 = (T & 1) << 7;
    const int k  = kg * 4 + kb;
    const int t  = j * 64 + k;
    const size_t rowBase = (size_t)(b * 1024 + t) * 16384;
    const int rbase = lane >> 2;
    const int ncol  = ns * 32 + (lane & 3) * 2;
#pragma unroll
    for (int mt = 0; mt < 4; mt++) {
        const int cl0 = wm * 64 + mt * 16 + rbase;
        float* p0 = out + rowBase + (size_t)(h0 + cl0) * 64 + ncol;
        float* p1 = p0 + 8 * 64;
#pragma unroll
        for (int nt = 0; nt < 4; nt++) {
            *reinterpret_cast<float2*>(p0 + nt * 8) =
                make_float2(acc[mt][nt][0], acc[mt][nt][1]);
            *reinterpret_cast<float2*>(p1 + nt * 8) =
                make_float2(acc[mt][nt][2], acc[mt][nt][3]);
        }
    }
}

__global__ void __launch_bounds__(512, 1) gemm_kernel(float* __restrict__ out) {
    extern __shared__ char smraw[];
    const uint32_t base = smem_u32(smraw);
    const int tid = threadIdx.x;
    const int T   = blockIdx.x;       // column tile
    const int kg  = blockIdx.y;       // group of 4 k-blocks

    const int sv = kg >> 2;           // steps = 5 + sv (uniform per CTA)
    if      (sv == 0) gemm_body<5>(base, tid, T, kg, out);
    else if (sv == 1) gemm_body<6>(base, tid, T, kg, out);
    else if (sv == 2) gemm_body<7>(base, tid, T, kg, out);
    else              gemm_body<8>(base, tid, T, kg, out);
}

// ---------------- launcher ----------------
extern "C" void kernel_launch(void* const* d_in, const int* in_sizes, int n_in,
                              void* d_out, int out_size) {
    const float* inp = (const float*)d_in[0];   // [4,1024,256]
    const float* A   = (const float*)d_in[1];   // [64,64]
    const float* Bv  = (const float*)d_in[2];   // [64]
    const float* x0  = (const float*)d_in[3];   // [4,256,64]
    float* out = (float*)d_out;

    squarings_kernel<<<1, 1024>>>(A);                       // 1
    transpose_kernel<<<dim3(32, 8, 4), dim3(32, 8)>>>(inp); // 2
    powers_kernel<<<64, 256>>>(Bv);                         // 3
    w_kernel<<<512, 256>>>();                               // 4
    vscan_kernel<<<128, 256>>>(x0);                         // 5

    cudaFuncSetAttribute(gemm_kernel,
                         cudaFuncAttributeMaxDynamicSharedMemorySize, GEMM_SMEM);
    dim3 grid(128, 16);
    gemm_kernel<<<grid, 512, GEMM_SMEM>>>(out);             // 6 <- ncu -s 5
}

// round 7
// speedup vs baseline: 3.8679x; 1.1977x over previous
#include <cuda_runtime.h>
#include <cuda_fp16.h>
#include <cstdint>
#include <cstddef>

// out = W[4096x128] @ Aug[128x16384] via mma.sync fp16 (single term).
// W row-block k = [A^{k+1} | tri(K_d)]; Aug col = [E_chunk ; u_chunk].

#define NCHUNK 16
#define BHTOT  1024
#define NCOLS  (NCHUNK * BHTOT)   // 16384

// ---------------- scratch (static device memory) --------------------------
__device__ float g_P[65 * 4096];            // P[m] = A^m
__device__ float g_Kvec[64 * 64];           // K_d = A^d B
__device__ float g_UT[(size_t)BHTOT * 1024];     // input transposed [bh][seq]
__device__ __align__(16) __half g_WH[64 * 8192];            // W fp16, per k 64x128
__device__ __align__(16) __half g_AugH[(size_t)NCOLS * 128];  // fp16(Aug)

// ---------------- helpers ----------------
__device__ __forceinline__ uint32_t smem_u32(const void* p) {
    uint32_t a;
    asm("{ .reg .u64 t; cvta.to.shared.u64 t, %1; cvt.u32.u64 %0, t; }"
        : "=r"(a) : "l"(p));
    return a;
}
__device__ __forceinline__ void ldsm4(uint32_t* r, uint32_t addr) {
    asm volatile("ldmatrix.sync.aligned.m8n8.x4.shared.b16 {%0,%1,%2,%3}, [%4];"
                 : "=r"(r[0]), "=r"(r[1]), "=r"(r[2]), "=r"(r[3]) : "r"(addr));
}
__device__ __forceinline__ void mma16816(float* d, const uint32_t* a,
                                         const uint32_t* b) {
    asm volatile(
        "mma.sync.aligned.m16n8k16.row.col.f32.f16.f16.f32 "
        "{%0,%1,%2,%3},{%4,%5,%6,%7},{%8,%9},{%0,%1,%2,%3};"
        : "+f"(d[0]), "+f"(d[1]), "+f"(d[2]), "+f"(d[3])
        : "r"(a[0]), "r"(a[1]), "r"(a[2]), "r"(a[3]), "r"(b[0]), "r"(b[1]));
}
__device__ __forceinline__ void cp16(uint32_t dst, const void* src) {
    asm volatile("cp.async.cg.shared.global [%0], [%1], 16;"
                 :: "r"(dst), "l"(src));
}
__device__ __forceinline__ void cp_commit() {
    asm volatile("cp.async.commit_group;" ::: "memory");
}
template <int N>
__device__ __forceinline__ void cp_wait_n() {
    asm volatile("cp.async.wait_group %0;" :: "n"(N) : "memory");
}

// ---------------- squarings: g_P[1]=A, g_P[2],4,8,16,32 -------------------
__global__ void __launch_bounds__(1024, 1) squarings_kernel(const float* __restrict__ A) {
    __shared__ float s0[64 * 65];
    __shared__ float s1[64 * 65];
    const int tid = threadIdx.x;
    for (int i = tid; i < 4096; i += 1024) {
        float v = A[i];
        s0[(i >> 6) * 65 + (i & 63)] = v;
        g_P[4096 + i] = v;
    }
    __syncthreads();
    float* src = s0;
    float* dst = s1;
    int p = 2;
    const int r  = tid >> 4;
    const int c0 = (tid & 15) * 4;
#pragma unroll 1
    for (int st = 0; st < 5; st++) {
        float a0 = 0, a1 = 0, a2 = 0, a3 = 0;
#pragma unroll 8
        for (int q = 0; q < 64; q++) {
            float av = src[r * 65 + q];
            a0 = fmaf(av, src[q * 65 + c0 + 0], a0);
            a1 = fmaf(av, src[q * 65 + c0 + 1], a1);
            a2 = fmaf(av, src[q * 65 + c0 + 2], a2);
            a3 = fmaf(av, src[q * 65 + c0 + 3], a3);
        }
        dst[r * 65 + c0 + 0] = a0;
        dst[r * 65 + c0 + 1] = a1;
        dst[r * 65 + c0 + 2] = a2;
        dst[r * 65 + c0 + 3] = a3;
        float* Po = g_P + (size_t)p * 4096 + r * 64 + c0;
        Po[0] = a0; Po[1] = a1; Po[2] = a2; Po[3] = a3;
        __syncthreads();
        float* t = src; src = dst; dst = t;
        p <<= 1;
    }
}

// ---------------- transpose input -> g_UT[bh][seq] + Aug u-half -----------
__global__ void transpose_kernel(const float* __restrict__ inp) {
    __shared__ float tile[32][33];
    const int tx = threadIdx.x, ty = threadIdx.y;     // 32 x 8
    const int t0 = blockIdx.x * 32, h0 = blockIdx.y * 32, b = blockIdx.z;
    const float* src = inp + (size_t)b * 1024 * 256;
#pragma unroll
    for (int i2 = 0; i2 < 4; i2++) {
        int row = ty + 8 * i2;
        tile[row][tx] = src[(size_t)(t0 + row) * 256 + h0 + tx];
    }
    __syncthreads();
    const int j = t0 >> 6;            // chunk (t0 is 32-aligned, within one chunk)
    const int s0 = t0 & 63;
#pragma unroll
    for (int i2 = 0; i2 < 4; i2++) {
        int hr = ty + 8 * i2;
        int bh = b * 256 + h0 + hr;
        float v = tile[tx][hr];
        g_UT[(size_t)bh * 1024 + t0 + tx] = v;
        g_AugH[(size_t)(j * 1024 + bh) * 128 + 64 + s0 + tx] = __float2half(v);
    }
}

// ---------------- powers: CTA c computes P[c+1], K_{c+1}, W P-half --------
__global__ void __launch_bounds__(256, 1) powers_kernel(const float* __restrict__ Bv) {
    __shared__ float cur[64 * 65];
    __shared__ float fac[64 * 65];
    __shared__ float bs[64];
    const int c = blockIdx.x;     // 0..63
    const int e = c + 1;          // 1..64
    const int tid = threadIdx.x;

    int low, rem;
    if (e == 64) { low = 32; rem = 32; }
    else         { low = e & (-e); rem = e - low; }

    for (int i = tid; i < 4096; i += 256)
        cur[(i >> 6) * 65 + (i & 63)] = g_P[(size_t)low * 4096 + i];
    if (tid < 64) bs[tid] = Bv[tid];

    const int rg = tid >> 4;
    const int cg = tid & 15;
    while (rem) {
        int b = rem & (-rem);
        rem -= b;
        for (int i = tid; i < 4096; i += 256)
            fac[(i >> 6) * 65 + (i & 63)] = g_P[(size_t)b * 4096 + i];
        __syncthreads();
        float acc[4][4];
#pragma unroll
        for (int r = 0; r < 4; r++)
#pragma unroll
            for (int cc = 0; cc < 4; cc++) acc[r][cc] = 0.0f;
#pragma unroll 4
        for (int q = 0; q < 64; q++) {
            float a0 = cur[(rg * 4 + 0) * 65 + q];
            float a1 = cur[(rg * 4 + 1) * 65 + q];
            float a2 = cur[(rg * 4 + 2) * 65 + q];
            float a3 = cur[(rg * 4 + 3) * 65 + q];
            float b0 = fac[q * 65 + cg * 4 + 0];
            float b1 = fac[q * 65 + cg * 4 + 1];
            float b2 = fac[q * 65 + cg * 4 + 2];
            float b3 = fac[q * 65 + cg * 4 + 3];
            acc[0][0] = fmaf(a0, b0, acc[0][0]); acc[0][1] = fmaf(a0, b1, acc[0][1]);
            acc[0][2] = fmaf(a0, b2, acc[0][2]); acc[0][3] = fmaf(a0, b3, acc[0][3]);
            acc[1][0] = fmaf(a1, b0, acc[1][0]); acc[1][1] = fmaf(a1, b1, acc[1][1]);
            acc[1][2] = fmaf(a1, b2, acc[1][2]); acc[1][3] = fmaf(a1, b3, acc[1][3]);
            acc[2][0] = fmaf(a2, b0, acc[2][0]); acc[2][1] = fmaf(a2, b1, acc[2][1]);
            acc[2][2] = fmaf(a2, b2, acc[2][2]); acc[2][3] = fmaf(a2, b3, acc[2][3]);
            acc[3][0] = fmaf(a3, b0, acc[3][0]); acc[3][1] = fmaf(a3, b1, acc[3][1]);
            acc[3][2] = fmaf(a3, b2, acc[3][2]); acc[3][3] = fmaf(a3, b3, acc[3][3]);
        }
        __syncthreads();
#pragma unroll
        for (int r = 0; r < 4; r++)
#pragma unroll
            for (int cc = 0; cc < 4; cc++)
                cur[(rg * 4 + r) * 65 + cg * 4 + cc] = acc[r][cc];
        __syncthreads();
    }
    for (int i = tid; i < 4096; i += 256)
        g_P[(size_t)e * 4096 + i] = cur[(i >> 6) * 65 + (i & 63)];
    // W P-half for block k = c: WH[k][n][m] = fp16(P[k+1][n][m]), m<64
    for (int i = tid; i < 4096; i += 256) {
        int n = i >> 6, m = i & 63;
        g_WH[(size_t)c * 8192 + n * 128 + m] = __float2half(cur[n * 65 + m]);
    }
    __syncthreads();
    if (e <= 63) {
        for (int n = tid; n < 64; n += 256) {
            float a = 0.0f;
#pragma unroll 8
            for (int q = 0; q < 64; q++) a = fmaf(cur[n * 65 + q], bs[q], a);
            g_Kvec[e * 64 + n] = a;
        }
    }
    if (c == 0 && tid < 64) g_Kvec[tid] = bs[tid];
}

// ---------------- W K-half (triangle): grid 256, 4 CTAs per k -------------
__global__ void w_kernel() {
    int k = blockIdx.x >> 2, seg = blockIdx.x & 3, tid = threadIdx.x;
    int i0 = seg * 1024;
    for (int idx = i0 + tid; idx < i0 + 1024; idx += 256) {
        int n = idx >> 6, s = idx & 63;     // 4096 K-half elements
        float val = (s <= k) ? g_Kvec[(k - s) * 64 + n] : 0.0f;
        g_WH[(size_t)k * 8192 + n * 128 + 64 + s] = __float2half(val);
    }
}

// ---------------- fused v + boundary scan + Aug E-half --------------------
__global__ void vscan_kernel(const float* __restrict__ x0) {
    __shared__ float sK[4096];
    __shared__ float sP[64 * 65];
    __shared__ float su[8][64];
    __shared__ float sbuf[8][64];
    int tid = threadIdx.x;
    for (int i = tid; i < 4096; i += 256) {
        sK[i] = g_Kvec[i];
        sP[(i >> 6) * 65 + (i & 63)] = g_P[(size_t)64 * 4096 + i];
    }
    __syncthreads();
    int w = tid >> 5, lane = tid & 31;
    int bh = blockIdx.x * 8 + w;
    const float* up = g_UT + (size_t)bh * 1024;
    float s0 = x0[(size_t)bh * 64 + lane];
    float s1 = x0[(size_t)bh * 64 + lane + 32];
    g_AugH[(size_t)bh * 128 + lane]      = __float2half(s0);
    g_AugH[(size_t)bh * 128 + lane + 32] = __float2half(s1);
#pragma unroll 1
    for (int j = 1; j < 16; j++) {
        su[w][lane]      = up[(j - 1) * 64 + lane];
        su[w][lane + 32] = up[(j - 1) * 64 + lane + 32];
        sbuf[w][lane]      = s0;
        sbuf[w][lane + 32] = s1;
        __syncwarp();
        float a0 = 0.0f, a1 = 0.0f;
#pragma unroll 8
        for (int s = 0; s < 64; s++) {
            float u = su[w][s];
            a0 = fmaf(sK[(63 - s) * 64 + lane], u, a0);
            a1 = fmaf(sK[(63 - s) * 64 + lane + 32], u, a1);
        }
#pragma unroll 8
        for (int q = 0; q < 64; q++) {
            float xq = sbuf[w][q];
            a0 = fmaf(sP[lane * 65 + q], xq, a0);
            a1 = fmaf(sP[(lane + 32) * 65 + q], xq, a1);
        }
        __syncwarp();
        s0 = a0; s1 = a1;
        g_AugH[(size_t)(j * 1024 + bh) * 128 + lane]      = __float2half(s0);
        g_AugH[(size_t)(j * 1024 + bh) * 128 + lane + 32] = __float2half(s1);
    }
}

// ---------------- mma.sync GEMM (fp16 single-term) ----------------
// CTA (512 thr, 16 warps): 128 Aug cols x 4 k-blocks (256 W rows).
// Warp: wm=wid>>3 (M half 64), ns=(wid>>2)&1 (32-row N half), kb=wid&3.
// smem pitch 272 B: Aug rows 0-127; W rows 128-383 (64 per kb).
#define PITCH    272
#define SM_WROW  128
#define GEMM_SMEM (384 * 272)    // 104448

__device__ __forceinline__ void load_pair(uint32_t base, int tid, int T,
                                          int kg, int p) {
    for (int i = tid; i < 1536; i += 512) {
        int row = i >> 2, q = i & 3;
        uint32_t dst = base + row * PITCH + p * 64 + q * 16;
        const __half* src;
        if (row < 128) {
            src = g_AugH + ((size_t)(T * 128 + row)) * 128;
        } else {
            int w2 = row - 128;                // 0..255
            int kb = w2 >> 6, r = w2 & 63;
            src = g_WH + ((size_t)((kg * 4 + kb) * 64 + r)) * 128;
        }
        cp16(dst, src + p * 32 + q * 8);
    }
    cp_commit();
}

template <int NP>
__device__ __forceinline__ void wait_pair(int p) {
    int pending = NP - 1 - p;
    if (pending <= 0)      cp_wait_n<0>();
    else if (pending == 1) cp_wait_n<1>();
    else if (pending == 2) cp_wait_n<2>();
    else                   cp_wait_n<3>();
}

template <int STEPS>
__device__ __forceinline__ void gemm_body(uint32_t base, int tid, int T,
                                          int kg, float* __restrict__ out) {
    const int wid = tid >> 5, lane = tid & 31;
    const int kb = wid & 3, ns = (wid >> 2) & 1, wm = wid >> 3;
    constexpr int NP = (STEPS + 1) / 2;

#pragma unroll
    for (int p = 0; p < NP; p++) load_pair(base, tid, T, kg, p);

    const uint32_t aRow = (lane & 7) + ((lane >> 3) & 1) * 8;
    const uint32_t aOff = ((lane >> 4) & 1) * 16;
    const uint32_t aH = base + (wm * 64 + aRow) * PITCH + aOff;
    const uint32_t bRow = (lane & 7) + ((lane >> 4) & 1) * 8;
    const uint32_t bOff = ((lane >> 3) & 1) * 16;
    const uint32_t wHa = base + (SM_WROW + kb * 64 + ns * 32 + bRow) * PITCH + bOff;

    float acc[4][4][4];
#pragma unroll
    for (int mt = 0; mt < 4; mt++)
#pragma unroll
        for (int nt = 0; nt < 4; nt++)
#pragma unroll
            for (int r = 0; r < 4; r++) acc[mt][nt][r] = 0.0f;

#pragma unroll
    for (int s = 0; s < STEPS; s++) {
        if ((s & 1) == 0) {
            wait_pair<NP>(s >> 1);
            __syncthreads();
        }
        uint32_t ah[4][4];
#pragma unroll
        for (int mt = 0; mt < 4; mt++)
            ldsm4(ah[mt], aH + mt * (16 * PITCH) + s * 32);
        uint32_t wh[2][4];
        ldsm4(wh[0], wHa + s * 32);
        ldsm4(wh[1], wHa + 16 * PITCH + s * 32);
#pragma unroll
        for (int mt = 0; mt < 4; mt++)
#pragma unroll
            for (int nt = 0; nt < 4; nt++)
                mma16816(acc[mt][nt], ah[mt], &wh[nt >> 1][(nt & 1) * 2]);
    }

    // ---- epilogue: coalesced float2 stores ----
    const int j  = T >> 3;
    const int b  = (T >> 1) & 3;
    const int h0 = (T & 1) << 7;
    const int k  = kg * 4 + kb;
    const int t  = j * 64 + k;
    const size_t rowBase = (size_t)(b * 1024 + t) * 16384;
    const int rbase = lane >> 2;
    const int ncol  = ns * 32 + (lane & 3) * 2;
#pragma unroll
    for (int mt = 0; mt < 4; mt++) {
        const int cl0 = wm * 64 + mt * 16 + rbase;
        float* p0 = out + rowBase + (size_t)(h0 + cl0) * 64 + ncol;
        float* p1 = p0 + 8 * 64;
#pragma unroll
        for (int nt = 0; nt < 4; nt++) {
            *reinterpret_cast<float2*>(p0 + nt * 8) =
                make_float2(acc[mt][nt][0], acc[mt][nt][1]);
            *reinterpret_cast<float2*>(p1 + nt * 8) =
                make_float2(acc[mt][nt][2], acc[mt][nt][3]);
        }
    }
}

__global__ void __launch_bounds__(512, 1) gemm_kernel(float* __restrict__ out) {
    extern __shared__ char smraw[];
    const uint32_t base = smem_u32(smraw);
    const int tid = threadIdx.x;
    const int T   = blockIdx.x;       // column tile
    const int kg  = blockIdx.y;       // group of 4 k-blocks

    const int sv = kg >> 2;           // steps = 5 + sv (uniform per CTA)
    if      (sv == 0) gemm_body<5>(base, tid, T, kg, out);
    else if (sv == 1) gemm_body<6>(base, tid, T, kg, out);
    else if (sv == 2) gemm_body<7>(base, tid, T, kg, out);
    else              gemm_body<8>(base, tid, T, kg, out);
}

// ---------------- launcher ----------------
extern "C" void kernel_launch(void* const* d_in, const int* in_sizes, int n_in,
                              void* d_out, int out_size) {
    const float* inp = (const float*)d_in[0];   // [4,1024,256]
    const float* A   = (const float*)d_in[1];   // [64,64]
    const float* Bv  = (const float*)d_in[2];   // [64]
    const float* x0  = (const float*)d_in[3];   // [4,256,64]
    float* out = (float*)d_out;

    squarings_kernel<<<1, 1024>>>(A);                       // 1
    transpose_kernel<<<dim3(32, 8, 4), dim3(32, 8)>>>(inp); // 2
    powers_kernel<<<64, 256>>>(Bv);                         // 3
    w_kernel<<<256, 256>>>();                               // 4
    vscan_kernel<<<128, 256>>>(x0);                         // 5

    cudaFuncSetAttribute(gemm_kernel,
                         cudaFuncAttributeMaxDynamicSharedMemorySize, GEMM_SMEM);
    dim3 grid(128, 16);
    gemm_kernel<<<grid, 512, GEMM_SMEM>>>(out);             // 6
}

// round 8
// speedup vs baseline: 3.8759x; 1.0021x over previous
#include <cuda_runtime.h>
#include <cuda_fp16.h>
#include <cstdint>
#include <cstddef>

// out = W[4096x128] @ Aug[128x16384] via mma.sync fp16.
// Persistent GEMM: 128 CTAs, Aug tile resident, W double-buffered over 16 kg.

#define NCHUNK 16
#define BHTOT  1024
#define NCOLS  (NCHUNK * BHTOT)   // 16384

// ---------------- scratch (static device memory) --------------------------
__device__ float g_P[65 * 4096];            // P[m] = A^m
__device__ float g_Kvec[64 * 64];           // K_d = A^d B
__device__ float g_UT[(size_t)BHTOT * 1024];     // input transposed [bh][seq]
__device__ __align__(16) __half g_WH[64 * 8192];            // W fp16, per k 64x128
__device__ __align__(16) __half g_AugH[(size_t)NCOLS * 128];  // fp16(Aug)

// ---------------- helpers ----------------
__device__ __forceinline__ uint32_t smem_u32(const void* p) {
    uint32_t a;
    asm("{ .reg .u64 t; cvta.to.shared.u64 t, %1; cvt.u32.u64 %0, t; }"
        : "=r"(a) : "l"(p));
    return a;
}
__device__ __forceinline__ void ldsm4(uint32_t* r, uint32_t addr) {
    asm volatile("ldmatrix.sync.aligned.m8n8.x4.shared.b16 {%0,%1,%2,%3}, [%4];"
                 : "=r"(r[0]), "=r"(r[1]), "=r"(r[2]), "=r"(r[3]) : "r"(addr));
}
__device__ __forceinline__ void mma16816(float* d, const uint32_t* a,
                                         const uint32_t* b) {
    asm volatile(
        "mma.sync.aligned.m16n8k16.row.col.f32.f16.f16.f32 "
        "{%0,%1,%2,%3},{%4,%5,%6,%7},{%8,%9},{%0,%1,%2,%3};"
        : "+f"(d[0]), "+f"(d[1]), "+f"(d[2]), "+f"(d[3])
        : "r"(a[0]), "r"(a[1]), "r"(a[2]), "r"(a[3]), "r"(b[0]), "r"(b[1]));
}
__device__ __forceinline__ void cp16(uint32_t dst, const void* src) {
    asm volatile("cp.async.cg.shared.global [%0], [%1], 16;"
                 :: "r"(dst), "l"(src));
}
__device__ __forceinline__ void cp_commit() {
    asm volatile("cp.async.commit_group;" ::: "memory");
}
template <int N>
__device__ __forceinline__ void cp_wait_n() {
    asm volatile("cp.async.wait_group %0;" :: "n"(N) : "memory");
}

// ---------------- squarings: g_P[1]=A, g_P[2],4,8,16,32 -------------------
__global__ void __launch_bounds__(1024, 1) squarings_kernel(const float* __restrict__ A) {
    __shared__ float s0[64 * 65];
    __shared__ float s1[64 * 65];
    const int tid = threadIdx.x;
    for (int i = tid; i < 4096; i += 1024) {
        float v = A[i];
        s0[(i >> 6) * 65 + (i & 63)] = v;
        g_P[4096 + i] = v;
    }
    __syncthreads();
    float* src = s0;
    float* dst = s1;
    int p = 2;
    const int r  = tid >> 4;
    const int c0 = (tid & 15) * 4;
#pragma unroll 1
    for (int st = 0; st < 5; st++) {
        float a0 = 0, a1 = 0, a2 = 0, a3 = 0;
#pragma unroll 8
        for (int q = 0; q < 64; q++) {
            float av = src[r * 65 + q];
            a0 = fmaf(av, src[q * 65 + c0 + 0], a0);
            a1 = fmaf(av, src[q * 65 + c0 + 1], a1);
            a2 = fmaf(av, src[q * 65 + c0 + 2], a2);
            a3 = fmaf(av, src[q * 65 + c0 + 3], a3);
        }
        dst[r * 65 + c0 + 0] = a0;
        dst[r * 65 + c0 + 1] = a1;
        dst[r * 65 + c0 + 2] = a2;
        dst[r * 65 + c0 + 3] = a3;
        float* Po = g_P + (size_t)p * 4096 + r * 64 + c0;
        Po[0] = a0; Po[1] = a1; Po[2] = a2; Po[3] = a3;
        __syncthreads();
        float* t = src; src = dst; dst = t;
        p <<= 1;
    }
}

// ---------------- transpose input -> g_UT[bh][seq] + Aug u-half -----------
__global__ void transpose_kernel(const float* __restrict__ inp) {
    __shared__ float tile[32][33];
    const int tx = threadIdx.x, ty = threadIdx.y;     // 32 x 8
    const int t0 = blockIdx.x * 32, h0 = blockIdx.y * 32, b = blockIdx.z;
    const float* src = inp + (size_t)b * 1024 * 256;
#pragma unroll
    for (int i2 = 0; i2 < 4; i2++) {
        int row = ty + 8 * i2;
        tile[row][tx] = src[(size_t)(t0 + row) * 256 + h0 + tx];
    }
    __syncthreads();
    const int j = t0 >> 6;
    const int s0 = t0 & 63;
#pragma unroll
    for (int i2 = 0; i2 < 4; i2++) {
        int hr = ty + 8 * i2;
        int bh = b * 256 + h0 + hr;
        float v = tile[tx][hr];
        g_UT[(size_t)bh * 1024 + t0 + tx] = v;
        g_AugH[(size_t)(j * 1024 + bh) * 128 + 64 + s0 + tx] = __float2half(v);
    }
}

// ---------------- powers: CTA c computes P[c+1], K_{c+1}, W P-half --------
__global__ void __launch_bounds__(256, 1) powers_kernel(const float* __restrict__ Bv) {
    __shared__ float cur[64 * 65];
    __shared__ float fac[64 * 65];
    __shared__ float bs[64];
    const int c = blockIdx.x;     // 0..63
    const int e = c + 1;          // 1..64
    const int tid = threadIdx.x;

    int low, rem;
    if (e == 64) { low = 32; rem = 32; }
    else         { low = e & (-e); rem = e - low; }

    for (int i = tid; i < 4096; i += 256)
        cur[(i >> 6) * 65 + (i & 63)] = g_P[(size_t)low * 4096 + i];
    if (tid < 64) bs[tid] = Bv[tid];

    const int rg = tid >> 4;
    const int cg = tid & 15;
    while (rem) {
        int b = rem & (-rem);
        rem -= b;
        for (int i = tid; i < 4096; i += 256)
            fac[(i >> 6) * 65 + (i & 63)] = g_P[(size_t)b * 4096 + i];
        __syncthreads();
        float acc[4][4];
#pragma unroll
        for (int r = 0; r < 4; r++)
#pragma unroll
            for (int cc = 0; cc < 4; cc++) acc[r][cc] = 0.0f;
#pragma unroll 4
        for (int q = 0; q < 64; q++) {
            float a0 = cur[(rg * 4 + 0) * 65 + q];
            float a1 = cur[(rg * 4 + 1) * 65 + q];
            float a2 = cur[(rg * 4 + 2) * 65 + q];
            float a3 = cur[(rg * 4 + 3) * 65 + q];
            float b0 = fac[q * 65 + cg * 4 + 0];
            float b1 = fac[q * 65 + cg * 4 + 1];
            float b2 = fac[q * 65 + cg * 4 + 2];
            float b3 = fac[q * 65 + cg * 4 + 3];
            acc[0][0] = fmaf(a0, b0, acc[0][0]); acc[0][1] = fmaf(a0, b1, acc[0][1]);
            acc[0][2] = fmaf(a0, b2, acc[0][2]); acc[0][3] = fmaf(a0, b3, acc[0][3]);
            acc[1][0] = fmaf(a1, b0, acc[1][0]); acc[1][1] = fmaf(a1, b1, acc[1][1]);
            acc[1][2] = fmaf(a1, b2, acc[1][2]); acc[1][3] = fmaf(a1, b3, acc[1][3]);
            acc[2][0] = fmaf(a2, b0, acc[2][0]); acc[2][1] = fmaf(a2, b1, acc[2][1]);
            acc[2][2] = fmaf(a2, b2, acc[2][2]); acc[2][3] = fmaf(a2, b3, acc[2][3]);
            acc[3][0] = fmaf(a3, b0, acc[3][0]); acc[3][1] = fmaf(a3, b1, acc[3][1]);
            acc[3][2] = fmaf(a3, b2, acc[3][2]); acc[3][3] = fmaf(a3, b3, acc[3][3]);
        }
        __syncthreads();
#pragma unroll
        for (int r = 0; r < 4; r++)
#pragma unroll
            for (int cc = 0; cc < 4; cc++)
                cur[(rg * 4 + r) * 65 + cg * 4 + cc] = acc[r][cc];
        __syncthreads();
    }
    for (int i = tid; i < 4096; i += 256)
        g_P[(size_t)e * 4096 + i] = cur[(i >> 6) * 65 + (i & 63)];
    for (int i = tid; i < 4096; i += 256) {
        int n = i >> 6, m = i & 63;
        g_WH[(size_t)c * 8192 + n * 128 + m] = __float2half(cur[n * 65 + m]);
    }
    __syncthreads();
    if (e <= 63) {
        for (int n = tid; n < 64; n += 256) {
            float a = 0.0f;
#pragma unroll 8
            for (int q = 0; q < 64; q++) a = fmaf(cur[n * 65 + q], bs[q], a);
            g_Kvec[e * 64 + n] = a;
        }
    }
    if (c == 0 && tid < 64) g_Kvec[tid] = bs[tid];
}

// ---------------- W K-half (triangle): grid 256, 4 CTAs per k -------------
__global__ void w_kernel() {
    int k = blockIdx.x >> 2, seg = blockIdx.x & 3, tid = threadIdx.x;
    int i0 = seg * 1024;
    for (int idx = i0 + tid; idx < i0 + 1024; idx += 256) {
        int n = idx >> 6, s = idx & 63;
        float val = (s <= k) ? g_Kvec[(k - s) * 64 + n] : 0.0f;
        g_WH[(size_t)k * 8192 + n * 128 + 64 + s] = __float2half(val);
    }
}

// ---------------- fused v + boundary scan + Aug E-half --------------------
__global__ void vscan_kernel(const float* __restrict__ x0) {
    __shared__ float sK[4096];
    __shared__ float sP[64 * 65];
    __shared__ float su[8][64];
    __shared__ float sbuf[8][64];
    int tid = threadIdx.x;
    for (int i = tid; i < 4096; i += 256) {
        sK[i] = g_Kvec[i];
        sP[(i >> 6) * 65 + (i & 63)] = g_P[(size_t)64 * 4096 + i];
    }
    __syncthreads();
    int w = tid >> 5, lane = tid & 31;
    int bh = blockIdx.x * 8 + w;
    const float* up = g_UT + (size_t)bh * 1024;
    float s0 = x0[(size_t)bh * 64 + lane];
    float s1 = x0[(size_t)bh * 64 + lane + 32];
    g_AugH[(size_t)bh * 128 + lane]      = __float2half(s0);
    g_AugH[(size_t)bh * 128 + lane + 32] = __float2half(s1);
#pragma unroll 1
    for (int j = 1; j < 16; j++) {
        su[w][lane]      = up[(j - 1) * 64 + lane];
        su[w][lane + 32] = up[(j - 1) * 64 + lane + 32];
        sbuf[w][lane]      = s0;
        sbuf[w][lane + 32] = s1;
        __syncwarp();
        float a0 = 0.0f, a1 = 0.0f;
#pragma unroll 8
        for (int s = 0; s < 64; s++) {
            float u = su[w][s];
            a0 = fmaf(sK[(63 - s) * 64 + lane], u, a0);
            a1 = fmaf(sK[(63 - s) * 64 + lane + 32], u, a1);
        }
#pragma unroll 8
        for (int q = 0; q < 64; q++) {
            float xq = sbuf[w][q];
            a0 = fmaf(sP[lane * 65 + q], xq, a0);
            a1 = fmaf(sP[(lane + 32) * 65 + q], xq, a1);
        }
        __syncwarp();
        s0 = a0; s1 = a1;
        g_AugH[(size_t)(j * 1024 + bh) * 128 + lane]      = __float2half(s0);
        g_AugH[(size_t)(j * 1024 + bh) * 128 + lane + 32] = __float2half(s1);
    }
}

// ---------------- persistent mma.sync GEMM ----------------
// 128 CTAs (one per T tile), 512 thr, Aug resident, W double-buffered.
// smem pitch 272 B: Aug rows 0-127; W buf0 rows 128-383; buf1 rows 384-639.
#define PITCH    272
#define GEMM_SMEM (640 * 272)    // 174080

// prefetch W for k-group kg into buffer buf (rows 128 + buf*256 ..)
// only the first 2*steps 16B-chunks of each row are needed (triangular skip)
__device__ __forceinline__ void load_w(uint32_t base, int tid, int kg, int buf,
                                       int steps) {
    const int qmax = 2 * steps;
    const __half* wsrc = g_WH + (size_t)kg * 4 * 8192;   // 256 rows x 128
    uint32_t dst0 = base + (128 + buf * 256) * PITCH;
    for (int i = tid; i < 4096; i += 512) {
        int row = i >> 4, q = i & 15;
        if (q < qmax)
            cp16(dst0 + row * PITCH + q * 16, wsrc + (size_t)row * 128 + q * 8);
    }
    cp_commit();
}

template <int STEPS>
__device__ __forceinline__ void gemm_iter(uint32_t aH, uint32_t wBase,
                                          float* __restrict__ out,
                                          int T, int kg, int kb, int ns,
                                          int wm, int lane) {
    const uint32_t bRow = (lane & 7) + ((lane >> 4) & 1) * 8;
    const uint32_t bOff = ((lane >> 3) & 1) * 16;
    const uint32_t wHa = wBase + (kb * 64 + ns * 32 + bRow) * PITCH + bOff;

    float acc[4][4][4];
#pragma unroll
    for (int mt = 0; mt < 4; mt++)
#pragma unroll
        for (int nt = 0; nt < 4; nt++)
#pragma unroll
            for (int r = 0; r < 4; r++) acc[mt][nt][r] = 0.0f;

#pragma unroll
    for (int s = 0; s < STEPS; s++) {
        uint32_t ah[4][4];
#pragma unroll
        for (int mt = 0; mt < 4; mt++)
            ldsm4(ah[mt], aH + mt * (16 * PITCH) + s * 32);
        uint32_t wh[2][4];
        ldsm4(wh[0], wHa + s * 32);
        ldsm4(wh[1], wHa + 16 * PITCH + s * 32);
#pragma unroll
        for (int mt = 0; mt < 4; mt++)
#pragma unroll
            for (int nt = 0; nt < 4; nt++)
                mma16816(acc[mt][nt], ah[mt], &wh[nt >> 1][(nt & 1) * 2]);
    }

    // epilogue for this kg
    const int j  = T >> 3;
    const int b  = (T >> 1) & 3;
    const int h0 = (T & 1) << 7;
    const int k  = kg * 4 + kb;
    const int t  = j * 64 + k;
    const size_t rowBase = (size_t)(b * 1024 + t) * 16384;
    const int rbase = lane >> 2;
    const int ncol  = ns * 32 + (lane & 3) * 2;
#pragma unroll
    for (int mt = 0; mt < 4; mt++) {
        const int cl0 = wm * 64 + mt * 16 + rbase;
        float* p0 = out + rowBase + (size_t)(h0 + cl0) * 64 + ncol;
        float* p1 = p0 + 8 * 64;
#pragma unroll
        for (int nt = 0; nt < 4; nt++) {
            *reinterpret_cast<float2*>(p0 + nt * 8) =
                make_float2(acc[mt][nt][0], acc[mt][nt][1]);
            *reinterpret_cast<float2*>(p1 + nt * 8) =
                make_float2(acc[mt][nt][2], acc[mt][nt][3]);
        }
    }
}

__global__ void __launch_bounds__(512, 1) gemm_kernel(float* __restrict__ out) {
    extern __shared__ char smraw[];
    const uint32_t base = smem_u32(smraw);
    const int tid = threadIdx.x;
    const int wid = tid >> 5, lane = tid & 31;
    const int kb = wid & 3, ns = (wid >> 2) & 1, wm = wid >> 3;
    const int T = blockIdx.x;         // column tile 0..127

    // prologue: Aug tile (32 KB) + W buffer 0 (kg=0, steps=5), one group
    {
        const __half* asrc = g_AugH + (size_t)T * 128 * 128;
        for (int i = tid; i < 2048; i += 512) {
            int row = i >> 4, q = i & 15;
            cp16(base + row * PITCH + q * 16, asrc + (size_t)row * 128 + q * 8);
        }
        const __half* wsrc = g_WH;    // kg = 0
        uint32_t dst0 = base + 128 * PITCH;
        for (int i = tid; i < 4096; i += 512) {
            int row = i >> 4, q = i & 15;
            if (q < 10)               // steps(0) = 5
                cp16(dst0 + row * PITCH + q * 16, wsrc + (size_t)row * 128 + q * 8);
        }
        cp_commit();
    }

    const uint32_t aRow = (lane & 7) + ((lane >> 3) & 1) * 8;
    const uint32_t aOff = ((lane >> 4) & 1) * 16;
    const uint32_t aH = base + (wm * 64 + aRow) * PITCH + aOff;

#pragma unroll 1
    for (int kg = 0; kg < 16; kg++) {
        if (kg < 15) {
            load_w(base, tid, kg + 1, (kg + 1) & 1, 5 + ((kg + 1) >> 2));
            cp_wait_n<1>();
        } else {
            cp_wait_n<0>();
        }
        __syncthreads();
        const uint32_t wBase = base + (128 + (kg & 1) * 256) * PITCH;
        switch (kg >> 2) {
        case 0: gemm_iter<5>(aH, wBase, out, T, kg, kb, ns, wm, lane); break;
        case 1: gemm_iter<6>(aH, wBase, out, T, kg, kb, ns, wm, lane); break;
        case 2: gemm_iter<7>(aH, wBase, out, T, kg, kb, ns, wm, lane); break;
        default: gemm_iter<8>(aH, wBase, out, T, kg, kb, ns, wm, lane); break;
        }
        __syncthreads();
    }
}

// ---------------- launcher ----------------
extern "C" void kernel_launch(void* const* d_in, const int* in_sizes, int n_in,
                              void* d_out, int out_size) {
    const float* inp = (const float*)d_in[0];   // [4,1024,256]
    const float* A   = (const float*)d_in[1];   // [64,64]
    const float* Bv  = (const float*)d_in[2];   // [64]
    const float* x0  = (const float*)d_in[3];   // [4,256,64]
    float* out = (float*)d_out;

    squarings_kernel<<<1, 1024>>>(A);                       // 1
    transpose_kernel<<<dim3(32, 8, 4), dim3(32, 8)>>>(inp); // 2
    powers_kernel<<<64, 256>>>(Bv);                         // 3
    w_kernel<<<256, 256>>>();                               // 4
    vscan_kernel<<<128, 256>>>(x0);                         // 5

    cudaFuncSetAttribute(gemm_kernel,
                         cudaFuncAttributeMaxDynamicSharedMemorySize, GEMM_SMEM);
    gemm_kernel<<<128, 512, GEMM_SMEM>>>(out);              // 6
}

// round 9
// speedup vs baseline: 4.6555x; 1.2011x over previous
#include <cuda_runtime.h>
#include <cuda_fp16.h>
#include <cstdint>
#include <cstddef>

// out = W[4096x128] @ Aug[128x16384] via mma.sync fp16.
// Persistent GEMM: grid 256 (T x half), occ 2, Aug resident, W double-buffered.

#define NCHUNK 16
#define BHTOT  1024
#define NCOLS  (NCHUNK * BHTOT)   // 16384

// ---------------- scratch (static device memory) --------------------------
__device__ float g_P64[4096];               // A^64
__device__ float g_Kvec[64 * 64];           // K_d = A^d B
__device__ float g_UT[(size_t)BHTOT * 1024];     // input transposed [bh][seq]
__device__ __align__(16) __half g_WH[64 * 8192];            // W fp16, per k 64x128
__device__ __align__(16) __half g_AugH[(size_t)NCOLS * 128];  // fp16(Aug)

// ---------------- helpers ----------------
__device__ __forceinline__ uint32_t smem_u32(const void* p) {
    uint32_t a;
    asm("{ .reg .u64 t; cvta.to.shared.u64 t, %1; cvt.u32.u64 %0, t; }"
        : "=r"(a) : "l"(p));
    return a;
}
__device__ __forceinline__ void ldsm4(uint32_t* r, uint32_t addr) {
    asm volatile("ldmatrix.sync.aligned.m8n8.x4.shared.b16 {%0,%1,%2,%3}, [%4];"
                 : "=r"(r[0]), "=r"(r[1]), "=r"(r[2]), "=r"(r[3]) : "r"(addr));
}
__device__ __forceinline__ void mma16816(float* d, const uint32_t* a,
                                         const uint32_t* b) {
    asm volatile(
        "mma.sync.aligned.m16n8k16.row.col.f32.f16.f16.f32 "
        "{%0,%1,%2,%3},{%4,%5,%6,%7},{%8,%9},{%0,%1,%2,%3};"
        : "+f"(d[0]), "+f"(d[1]), "+f"(d[2]), "+f"(d[3])
        : "r"(a[0]), "r"(a[1]), "r"(a[2]), "r"(a[3]), "r"(b[0]), "r"(b[1]));
}
__device__ __forceinline__ void cp16(uint32_t dst, const void* src) {
    asm volatile("cp.async.cg.shared.global [%0], [%1], 16;"
                 :: "r"(dst), "l"(src));
}
__device__ __forceinline__ void cp_commit() {
    asm volatile("cp.async.commit_group;" ::: "memory");
}
template <int N>
__device__ __forceinline__ void cp_wait_n() {
    asm volatile("cp.async.wait_group %0;" :: "n"(N) : "memory");
}

// ---------------- in-CTA 64x64 matmul (pitch 65), 256 threads -------------
__device__ __forceinline__ void mm64(float* D, const float* Aa,
                                     const float* Bb, int tid) {
    const int rg = tid >> 4;
    const int cg = tid & 15;
    float acc[4][4];
#pragma unroll
    for (int r = 0; r < 4; r++)
#pragma unroll
        for (int c = 0; c < 4; c++) acc[r][c] = 0.0f;
#pragma unroll 4
    for (int q = 0; q < 64; q++) {
        float a0 = Aa[(rg * 4 + 0) * 65 + q];
        float a1 = Aa[(rg * 4 + 1) * 65 + q];
        float a2 = Aa[(rg * 4 + 2) * 65 + q];
        float a3 = Aa[(rg * 4 + 3) * 65 + q];
        float b0 = Bb[q * 65 + cg * 4 + 0];
        float b1 = Bb[q * 65 + cg * 4 + 1];
        float b2 = Bb[q * 65 + cg * 4 + 2];
        float b3 = Bb[q * 65 + cg * 4 + 3];
        acc[0][0] = fmaf(a0, b0, acc[0][0]); acc[0][1] = fmaf(a0, b1, acc[0][1]);
        acc[0][2] = fmaf(a0, b2, acc[0][2]); acc[0][3] = fmaf(a0, b3, acc[0][3]);
        acc[1][0] = fmaf(a1, b0, acc[1][0]); acc[1][1] = fmaf(a1, b1, acc[1][1]);
        acc[1][2] = fmaf(a1, b2, acc[1][2]); acc[1][3] = fmaf(a1, b3, acc[1][3]);
        acc[2][0] = fmaf(a2, b0, acc[2][0]); acc[2][1] = fmaf(a2, b1, acc[2][1]);
        acc[2][2] = fmaf(a2, b2, acc[2][2]); acc[2][3] = fmaf(a2, b3, acc[2][3]);
        acc[3][0] = fmaf(a3, b0, acc[3][0]); acc[3][1] = fmaf(a3, b1, acc[3][1]);
        acc[3][2] = fmaf(a3, b2, acc[3][2]); acc[3][3] = fmaf(a3, b3, acc[3][3]);
    }
#pragma unroll
    for (int r = 0; r < 4; r++)
#pragma unroll
        for (int c = 0; c < 4; c++)
            D[(rg * 4 + r) * 65 + cg * 4 + c] = acc[r][c];
    __syncthreads();
}

// ---------------- powers: CTA c = A^{c+1} (square&multiply), K, W P-half --
__global__ void __launch_bounds__(256, 1) powers_kernel(
    const float* __restrict__ A, const float* __restrict__ Bv) {
    __shared__ float b0s[64 * 65];
    __shared__ float b1s[64 * 65];
    __shared__ float b2s[64 * 65];
    __shared__ float bs[64];
    float* pw  = b0s;
    float* res = b1s;
    float* tmp = b2s;
    const int c = blockIdx.x;     // 0..63
    const int e = c + 1;          // 1..64
    const int tid = threadIdx.x;

    for (int i = tid; i < 4096; i += 256)
        pw[(i >> 6) * 65 + (i & 63)] = A[i];
    if (tid < 64) bs[tid] = Bv[tid];
    __syncthreads();

    bool has = false;
    int rem = e;
    while (true) {
        if (rem & 1) {
            if (!has) {
                for (int i = tid; i < 4096; i += 256) {
                    int o = (i >> 6) * 65 + (i & 63);
                    res[o] = pw[o];
                }
                __syncthreads();
                has = true;
            } else {
                mm64(tmp, res, pw, tid);
                float* t = res; res = tmp; tmp = t;
            }
        }
        rem >>= 1;
        if (!rem) break;
        mm64(tmp, pw, pw, tid);
        float* t = pw; pw = tmp; tmp = t;
    }
    // res = A^e
    if (e == 64) {
        for (int i = tid; i < 4096; i += 256)
            g_P64[i] = res[(i >> 6) * 65 + (i & 63)];
    }
    // W P-half for block k = c
    for (int i = tid; i < 4096; i += 256) {
        int n = i >> 6, m = i & 63;
        g_WH[(size_t)c * 8192 + n * 128 + m] = __float2half(res[n * 65 + m]);
    }
    // K vectors
    if (e <= 63) {
        for (int n = tid; n < 64; n += 256) {
            float a = 0.0f;
#pragma unroll 8
            for (int q = 0; q < 64; q++) a = fmaf(res[n * 65 + q], bs[q], a);
            g_Kvec[e * 64 + n] = a;
        }
    }
    if (c == 0 && tid < 64) g_Kvec[tid] = bs[tid];
}

// ---------------- transpose input -> g_UT[bh][seq] + Aug u-half -----------
__global__ void transpose_kernel(const float* __restrict__ inp) {
    __shared__ float tile[32][33];
    const int tx = threadIdx.x, ty = threadIdx.y;     // 32 x 8
    const int t0 = blockIdx.x * 32, h0 = blockIdx.y * 32, b = blockIdx.z;
    const float* src = inp + (size_t)b * 1024 * 256;
#pragma unroll
    for (int i2 = 0; i2 < 4; i2++) {
        int row = ty + 8 * i2;
        tile[row][tx] = src[(size_t)(t0 + row) * 256 + h0 + tx];
    }
    __syncthreads();
    const int j = t0 >> 6;
    const int s0 = t0 & 63;
#pragma unroll
    for (int i2 = 0; i2 < 4; i2++) {
        int hr = ty + 8 * i2;
        int bh = b * 256 + h0 + hr;
        float v = tile[tx][hr];
        g_UT[(size_t)bh * 1024 + t0 + tx] = v;
        g_AugH[(size_t)(j * 1024 + bh) * 128 + 64 + s0 + tx] = __float2half(v);
    }
}

// ---------------- fused v + scan + Aug E-half + W K-half ------------------
__global__ void vscanw_kernel(const float* __restrict__ x0) {
    __shared__ float sK[4096];
    __shared__ float sP[64 * 65];
    __shared__ float su[8][64];
    __shared__ float sbuf[8][64];
    int tid = threadIdx.x;
    for (int i = tid; i < 4096; i += 256) {
        sK[i] = g_Kvec[i];
        sP[(i >> 6) * 65 + (i & 63)] = g_P64[i];
    }
    __syncthreads();

    // W K-half triangle: this CTA's 2048-element slice of 64x4096
    {
        int base_i = blockIdx.x * 2048;
        for (int ii = tid; ii < 2048; ii += 256) {
            int idx = base_i + ii;
            int k = idx >> 12, n = (idx >> 6) & 63, s = idx & 63;
            float val = (s <= k) ? sK[(k - s) * 64 + n] : 0.0f;
            g_WH[(size_t)k * 8192 + n * 128 + 64 + s] = __float2half(val);
        }
    }

    int w = tid >> 5, lane = tid & 31;
    int bh = blockIdx.x * 8 + w;
    const float* up = g_UT + (size_t)bh * 1024;
    float s0 = x0[(size_t)bh * 64 + lane];
    float s1 = x0[(size_t)bh * 64 + lane + 32];
    g_AugH[(size_t)bh * 128 + lane]      = __float2half(s0);
    g_AugH[(size_t)bh * 128 + lane + 32] = __float2half(s1);
#pragma unroll 1
    for (int j = 1; j < 16; j++) {
        su[w][lane]      = up[(j - 1) * 64 + lane];
        su[w][lane + 32] = up[(j - 1) * 64 + lane + 32];
        sbuf[w][lane]      = s0;
        sbuf[w][lane + 32] = s1;
        __syncwarp();
        float a0 = 0.0f, a1 = 0.0f;
#pragma unroll 8
        for (int s = 0; s < 64; s++) {
            float u = su[w][s];
            a0 = fmaf(sK[(63 - s) * 64 + lane], u, a0);
            a1 = fmaf(sK[(63 - s) * 64 + lane + 32], u, a1);
        }
#pragma unroll 8
        for (int q = 0; q < 64; q++) {
            float xq = sbuf[w][q];
            a0 = fmaf(sP[lane * 65 + q], xq, a0);
            a1 = fmaf(sP[(lane + 32) * 65 + q], xq, a1);
        }
        __syncwarp();
        s0 = a0; s1 = a1;
        g_AugH[(size_t)(j * 1024 + bh) * 128 + lane]      = __float2half(s0);
        g_AugH[(size_t)(j * 1024 + bh) * 128 + lane + 32] = __float2half(s1);
    }
}

// ---------------- persistent mma.sync GEMM, occupancy 2 -------------------
// grid 256: T = bid>>1 (128 Aug cols), nh = bid&1 (2 of 4 k-blocks per kg).
// smem pitch 272 B: Aug rows 0-127; W buf0 rows 128-255; buf1 rows 256-383.
// 16 warps: kb = wid&1, ns = (wid>>1)&1, wm = wid>>2 (M tile 32).
#define PITCH    272
#define GEMM_SMEM (384 * 272)    // 104448

__device__ __forceinline__ void load_w(uint32_t base, int tid, int kg, int nh,
                                       int buf, int steps) {
    const int qmax = 2 * steps;
    const __half* wsrc = g_WH + (size_t)(kg * 4 + nh * 2) * 64 * 128;  // 128 rows
    uint32_t dst0 = base + (128 + buf * 128) * PITCH;
    for (int i = tid; i < 2048; i += 512) {
        int row = i >> 4, q = i & 15;
        if (q < qmax)
            cp16(dst0 + row * PITCH + q * 16, wsrc + (size_t)row * 128 + q * 8);
    }
    cp_commit();
}

template <int STEPS>
__device__ __forceinline__ void gemm_iter(uint32_t aH, uint32_t wBase,
                                          float* __restrict__ out,
                                          int T, int nh, int kg, int kb,
                                          int ns, int wm, int lane) {
    const uint32_t bRow = (lane & 7) + ((lane >> 4) & 1) * 8;
    const uint32_t bOff = ((lane >> 3) & 1) * 16;
    const uint32_t wHa = wBase + (kb * 64 + ns * 32 + bRow) * PITCH + bOff;

    float acc[2][4][4];
#pragma unroll
    for (int mt = 0; mt < 2; mt++)
#pragma unroll
        for (int nt = 0; nt < 4; nt++)
#pragma unroll
            for (int r = 0; r < 4; r++) acc[mt][nt][r] = 0.0f;

#pragma unroll
    for (int s = 0; s < STEPS; s++) {
        uint32_t ah[2][4];
        ldsm4(ah[0], aH + s * 32);
        ldsm4(ah[1], aH + 16 * PITCH + s * 32);
        uint32_t wh[2][4];
        ldsm4(wh[0], wHa + s * 32);
        ldsm4(wh[1], wHa + 16 * PITCH + s * 32);
#pragma unroll
        for (int mt = 0; mt < 2; mt++)
#pragma unroll
            for (int nt = 0; nt < 4; nt++)
                mma16816(acc[mt][nt], ah[mt], &wh[nt >> 1][(nt & 1) * 2]);
    }

    // epilogue for this kg
    const int j  = T >> 3;
    const int b  = (T >> 1) & 3;
    const int h0 = (T & 1) << 7;
    const int k  = kg * 4 + nh * 2 + kb;
    const int t  = j * 64 + k;
    const size_t rowBase = (size_t)(b * 1024 + t) * 16384;
    const int rbase = lane >> 2;
    const int ncol  = ns * 32 + (lane & 3) * 2;
#pragma unroll
    for (int mt = 0; mt < 2; mt++) {
        const int cl0 = wm * 32 + mt * 16 + rbase;
        float* p0 = out + rowBase + (size_t)(h0 + cl0) * 64 + ncol;
        float* p1 = p0 + 8 * 64;
#pragma unroll
        for (int nt = 0; nt < 4; nt++) {
            *reinterpret_cast<float2*>(p0 + nt * 8) =
                make_float2(acc[mt][nt][0], acc[mt][nt][1]);
            *reinterpret_cast<float2*>(p1 + nt * 8) =
                make_float2(acc[mt][nt][2], acc[mt][nt][3]);
        }
    }
}

__global__ void __launch_bounds__(512, 2) gemm_kernel(float* __restrict__ out) {
    extern __shared__ char smraw[];
    const uint32_t base = smem_u32(smraw);
    const int tid = threadIdx.x;
    const int wid = tid >> 5, lane = tid & 31;
    const int kb = wid & 1, ns = (wid >> 1) & 1, wm = wid >> 2;
    const int T  = blockIdx.x >> 1;
    const int nh = blockIdx.x & 1;

    // prologue: Aug tile (32 KB) + W buffer 0 (kg=0, steps=5)
    {
        const __half* asrc = g_AugH + (size_t)T * 128 * 128;
        for (int i = tid; i < 2048; i += 512) {
            int row = i >> 4, q = i & 15;
            cp16(base + row * PITCH + q * 16, asrc + (size_t)row * 128 + q * 8);
        }
        const __half* wsrc = g_WH + (size_t)(nh * 2) * 64 * 128;   // kg = 0
        uint32_t dst0 = base + 128 * PITCH;
        for (int i = tid; i < 2048; i += 512) {
            int row = i >> 4, q = i & 15;
            if (q < 10)               // steps(kg=0) = 5
                cp16(dst0 + row * PITCH + q * 16, wsrc + (size_t)row * 128 + q * 8);
        }
        cp_commit();
    }

    const uint32_t aRow = (lane & 7) + ((lane >> 3) & 1) * 8;
    const uint32_t aOff = ((lane >> 4) & 1) * 16;
    const uint32_t aH = base + (wm * 32 + aRow) * PITCH + aOff;

#pragma unroll 1
    for (int kg = 0; kg < 16; kg++) {
        if (kg < 15) {
            load_w(base, tid, kg + 1, nh, (kg + 1) & 1, 5 + ((kg + 1) >> 2));
            cp_wait_n<1>();
        } else {
            cp_wait_n<0>();
        }
        __syncthreads();
        const uint32_t wBase = base + (128 + (kg & 1) * 128) * PITCH;
        switch (kg >> 2) {
        case 0: gemm_iter<5>(aH, wBase, out, T, nh, kg, kb, ns, wm, lane); break;
        case 1: gemm_iter<6>(aH, wBase, out, T, nh, kg, kb, ns, wm, lane); break;
        case 2: gemm_iter<7>(aH, wBase, out, T, nh, kg, kb, ns, wm, lane); break;
        default: gemm_iter<8>(aH, wBase, out, T, nh, kg, kb, ns, wm, lane); break;
        }
        __syncthreads();
    }
}

// ---------------- launcher ----------------
extern "C" void kernel_launch(void* const* d_in, const int* in_sizes, int n_in,
                              void* d_out, int out_size) {
    const float* inp = (const float*)d_in[0];   // [4,1024,256]
    const float* A   = (const float*)d_in[1];   // [64,64]
    const float* Bv  = (const float*)d_in[2];   // [64]
    const float* x0  = (const float*)d_in[3];   // [4,256,64]
    float* out = (float*)d_out;

    powers_kernel<<<64, 256>>>(A, Bv);                      // 1
    transpose_kernel<<<dim3(32, 8, 4), dim3(32, 8)>>>(inp); // 2
    vscanw_kernel<<<128, 256>>>(x0);                        // 3

    cudaFuncSetAttribute(gemm_kernel,
                         cudaFuncAttributeMaxDynamicSharedMemorySize, GEMM_SMEM);
    gemm_kernel<<<256, 512, GEMM_SMEM>>>(out);              // 4
}